// round 8
// baseline (speedup 1.0000x reference)
#include <cuda_runtime.h>
#include <cuda_bf16.h>
#include <math.h>

#define BB 256
#define NN 1024
#define NSL 8

// ---------------- device-global scratch (no runtime allocation allowed) ----------------
__device__ float g_k[BB*NN*64];
__device__ float g_v[BB*NN*64];
__device__ float g_logits[BB*NN];
__device__ float g_loga[BB*NN];
__device__ float g_slots[BB*NSL*64];
__device__ float g_q[BB*NSL*64];
__device__ float g_q2[BB*NSL];
__device__ float g_logb[BB*NSL];
__device__ float g_upd[BB*NSL*64];

__device__ __forceinline__ float wsum(float v){
  #pragma unroll
  for(int o=16;o;o>>=1) v += __shfl_xor_sync(0xffffffffu, v, o);
  return v;
}
__device__ __forceinline__ float wmax(float v){
  #pragma unroll
  for(int o=16;o;o>>=1) v = fmaxf(v, __shfl_xor_sync(0xffffffffu, v, o));
  return v;
}
__device__ __forceinline__ float sigf(float x){ return 1.f/(1.f+__expf(-x)); }

// ---------------- slots = mu + (|sigma|+eps)*noise ----------------
__global__ void k_init_slots(const float* __restrict__ noise, const float* __restrict__ mu,
                             const float* __restrict__ sig){
  int idx = blockIdx.x*256 + threadIdx.x;
  if(idx < BB*NSL*64){
    int d = idx & 63;
    g_slots[idx] = mu[d] + (fabsf(sig[d]) + 1e-8f) * noise[idx];
  }
}

// ---------------- LN(inputs), k/v projections, wi logits (8 rows per CTA) ----------------
__global__ void __launch_bounds__(256) k_prep(const float* __restrict__ inp,
        const float* __restrict__ lng, const float* __restrict__ lnb,
        const float* __restrict__ Wk, const float* __restrict__ Wv,
        const float* __restrict__ wiw, const float* __restrict__ wib){
  __shared__ float xs[8][64];
  int row0 = blockIdx.x*8;
  int tid = threadIdx.x, w = tid>>5, l = tid&31;
  {
    const float* xr = inp + (size_t)(row0+w)*64;
    float x0=xr[l], x1=xr[l+32];
    float s  = wsum(x0+x1);
    float s2 = wsum(x0*x0+x1*x1);
    float m  = s*(1.f/64.f);
    float var= s2*(1.f/64.f) - m*m;
    float rs = rsqrtf(var + 1e-5f);
    float xn0=(x0-m)*rs*lng[l]+lnb[l];
    float xn1=(x1-m)*rs*lng[l+32]+lnb[l+32];
    xs[w][l]=xn0; xs[w][l+32]=xn1;
    float lp = wsum(xn0*wiw[l] + xn1*wiw[l+32]);
    if(l==0) g_logits[row0+w] = lp + wib[0];
  }
  __syncthreads();
  int j = tid & 63, g = tid >> 6;   // g in 0..3: handles rows g and g+4
  float k0=0.f,k1=0.f,v0=0.f,v1=0.f;
  const float* wkr = Wk + j*64;
  const float* wvr = Wv + j*64;
  #pragma unroll 8
  for(int i=0;i<64;i++){
    float wk = wkr[i], wv2 = wvr[i];
    float a = xs[g][i], c = xs[g+4][i];
    k0 = fmaf(a,wk,k0);  k1 = fmaf(c,wk,k1);
    v0 = fmaf(a,wv2,v0); v1 = fmaf(c,wv2,v1);
  }
  g_k[(size_t)(row0+g)*64+j]=k0;   g_k[(size_t)(row0+g+4)*64+j]=k1;
  g_v[(size_t)(row0+g)*64+j]=v0;   g_v[(size_t)(row0+g+4)*64+j]=v1;
}

// ---------------- a = softmax(logits)*NS ; store log(a+eps) ----------------
__global__ void __launch_bounds__(256) k_softa(){
  int b = blockIdx.x, tid = threadIdx.x, w = tid>>5, l = tid&31;
  __shared__ float red[8];
  __shared__ float bcM, bcS;
  const float* lg = g_logits + b*1024;
  float mx=-1e30f;
  for(int n=tid;n<1024;n+=256) mx=fmaxf(mx,lg[n]);
  mx=wmax(mx);
  if(l==0) red[w]=mx;
  __syncthreads();
  if(tid==0){ float m=red[0]; for(int i=1;i<8;i++) m=fmaxf(m,red[i]); bcM=m; }
  __syncthreads();
  float M=bcM;
  float ss=0.f;
  for(int n=tid;n<1024;n+=256) ss += __expf(lg[n]-M);
  ss=wsum(ss);
  if(l==0) red[w]=ss;
  __syncthreads();
  if(tid==0){ float s=0.f; for(int i=0;i<8;i++) s+=red[i]; bcS=s; }
  __syncthreads();
  float invS = 8.f/bcS;
  for(int n=tid;n<1024;n+=256)
    g_loga[b*1024+n] = __logf(__expf(lg[n]-M)*invS + 1e-8f);
}

// ---------------- per-iter: LN(slots), bm softmax -> log b, q projection, |q|^2 ----------------
__global__ void __launch_bounds__(256) k_slotproj(const float* __restrict__ Wq,
        const float* __restrict__ lsg, const float* __restrict__ lsb,
        const float* __restrict__ wsw, const float* __restrict__ wsb){
  int b=blockIdx.x, tid=threadIdx.x, w=tid>>5, l=tid&31;
  __shared__ float sn[8][64];
  __shared__ float ls[8];
  const float* sr = g_slots + (b*8+w)*64;
  float x0=sr[l], x1=sr[l+32];
  float s1=wsum(x0+x1), s2=wsum(x0*x0+x1*x1);
  float m=s1*(1.f/64.f), var=s2*(1.f/64.f)-m*m;
  float rs=rsqrtf(var+1e-5f);
  float n0=(x0-m)*rs*lsg[l]+lsb[l];
  float n1=(x1-m)*rs*lsg[l+32]+lsb[l+32];
  sn[w][l]=n0; sn[w][l+32]=n1;
  float lp=wsum(n0*wsw[l]+n1*wsw[l+32]);
  if(l==0) ls[w]=lp+wsb[0];
  __syncthreads();
  if(tid==0){
    float M=ls[0];
    for(int i=1;i<8;i++) M=fmaxf(M,ls[i]);
    float S=0.f;
    for(int i=0;i<8;i++) S+=__expf(ls[i]-M);
    for(int i=0;i<8;i++)
      g_logb[b*8+i]=__logf(8.f*__expf(ls[i]-M)/S + 1e-8f);
  }
  float q0=0.f,q1=0.f;
  const float* w0=Wq+l*64; const float* w1=Wq+(l+32)*64;
  #pragma unroll 8
  for(int i=0;i<64;i++){ float si=sn[w][i]; q0=fmaf(si,w0[i],q0); q1=fmaf(si,w1[i],q1); }
  g_q[(b*8+w)*64+l]=q0;
  g_q[(b*8+w)*64+l+32]=q1;
  float qq=wsum(q0*q0+q1*q1);
  if(l==0) g_q2[b*8+w]=qq;
}

// ---------------- cdist + MESH (fwd + analytic bwd) + warm sinkhorn + P/updates/pos ----------------
// smem floats: C 8192 | G 8192 | U 8192 | la 1024 | du 1024 | qs 512 | vh 72 | lb 8 | q2 8 | dv 8 | wr 64
#define SM_G  8192
#define SM_U  16384
#define SM_LA 24576
#define SM_DU 25600
#define SM_QS 26624
#define SM_VH 27136
#define SM_LB 27208
#define SM_Q2 27216
#define SM_DV 27224
#define SM_WR 27232
#define SM_TOT 27296
#define SMEM_BYTES (SM_TOT*4)

#define OUT_POS  131072
#define OUT_ATTN 135168

__global__ void __launch_bounds__(256,2) k_batch(float* __restrict__ out, int last){
  extern __shared__ float sm[];
  float* C  = sm;
  float* G  = sm + SM_G;
  float* U  = sm + SM_U;
  float* la = sm + SM_LA;
  float* du = sm + SM_DU;
  float* qs = sm + SM_QS;
  float* vh = sm + SM_VH;   // v history [9][8]
  float* lb = sm + SM_LB;
  float* q2 = sm + SM_Q2;
  float* dv = sm + SM_DV;
  float* wr = sm + SM_WR;   // [8 warps][8]
  int b=blockIdx.x, tid=threadIdx.x, w=tid>>5, l=tid&31;

  for(int n=tid;n<1024;n+=256) la[n]=g_loga[b*1024+n];
  for(int i=tid;i<512;i+=256)  qs[i]=g_q[b*512+i];
  if(tid<8){ q2[tid]=g_q2[b*8+tid]; lb[tid]=g_logb[b*8+tid]; }
  __syncthreads();

  // ---- C[s][n] = ||k_n - q_s|| ----
  for(int r=0;r<4;r++){
    int n=r*256+tid;
    const float4* kr=(const float4*)(g_k+((size_t)(b*1024+n))*64);
    float dot[8]; float k2=0.f;
    #pragma unroll
    for(int s=0;s<8;s++) dot[s]=0.f;
    #pragma unroll
    for(int i=0;i<16;i++){
      float4 f=kr[i];
      k2=fmaf(f.x,f.x,fmaf(f.y,f.y,fmaf(f.z,f.z,fmaf(f.w,f.w,k2))));
      #pragma unroll
      for(int s=0;s<8;s++){
        const float* qp=qs+s*64+i*4;
        dot[s]=fmaf(f.x,qp[0],fmaf(f.y,qp[1],fmaf(f.z,qp[2],fmaf(f.w,qp[3],dot[s]))));
      }
    }
    #pragma unroll
    for(int s=0;s<8;s++)
      C[s*1024+n]=sqrtf(fmaxf(k2+q2[s]-2.f*dot[s],1e-12f));
  }
  __syncthreads();

  // ---- MESH: 4 x { sinkhorn fwd (store u_t,v_t); entropy direct terms; adjoint bwd; C -= 3*grad } ----
  for(int mesh=0;mesh<4;mesh++){
    if(tid<8) vh[tid]=0.f;              // v_0 = 0
    __syncthreads();
    // forward
    for(int it=0;it<8;it++){
      float vp[8];
      #pragma unroll
      for(int s=0;s<8;s++) vp[s]=vh[it*8+s];
      for(int r=0;r<4;r++){
        int n=r*256+tid;
        float arg[8]; float mx=-1e30f;
        #pragma unroll
        for(int s=0;s<8;s++){ arg[s]=vp[s]-C[s*1024+n]; mx=fmaxf(mx,arg[s]); }
        float ss=0.f;
        #pragma unroll
        for(int s=0;s<8;s++) ss+=__expf(arg[s]-mx);
        U[it*1024+n]=la[n]-(mx+__logf(ss));
      }
      __syncthreads();
      {
        const float* Cc=C+w*1024; const float* Uc=U+it*1024;
        float mx=-1e30f;
        for(int i=l;i<1024;i+=32) mx=fmaxf(mx,Uc[i]-Cc[i]);
        mx=wmax(mx);
        float ss=0.f;
        for(int i=l;i<1024;i+=32) ss+=__expf(Uc[i]-Cc[i]-mx);
        ss=wsum(ss);
        if(l==0) vh[(it+1)*8+w]=lb[w]-(mx+__logf(ss));
      }
      __syncthreads();
    }
    // entropy direct terms: G = t0 = P*(log(P+e)+P/(P+e)); du = -rowsum t0; dv = -colsum t0
    {
      float v8[8];
      #pragma unroll
      for(int s=0;s<8;s++) v8[s]=vh[64+s];
      for(int r=0;r<4;r++){
        int n=r*256+tid;
        float u8=U[7*1024+n]; float ra=0.f;
        #pragma unroll
        for(int s=0;s<8;s++){
          float P=__expf(u8+v8[s]-C[s*1024+n]);
          float Pe=P+1e-8f;
          float t0=P*(__logf(Pe)+__fdividef(P,Pe));
          G[s*1024+n]=t0; ra+=t0;
        }
        du[n]=-ra;
      }
      __syncthreads();
      float ss=0.f;
      for(int i=l;i<1024;i+=32) ss+=G[w*1024+i];
      ss=wsum(ss);
      if(l==0) dv[w]=-ss;
      __syncthreads();
    }
    // backward t = 8..1 (it = 7..0)
    for(int it=7;it>=0;it--){
      float vtf[8],vm[8],dvr[8],vacc[8];
      #pragma unroll
      for(int s=0;s<8;s++){
        vtf[s]=vh[(it+1)*8+s]-lb[s];
        vm[s]=vh[it*8+s];
        dvr[s]=dv[s];
        vacc[s]=0.f;
      }
      for(int r=0;r<4;r++){
        int n=r*256+tid;
        float ut=U[it*1024+n];
        float uacc=(it==7)?du[n]:0.f;
        float cv[8],wv[8];
        #pragma unroll
        for(int s=0;s<8;s++) cv[s]=C[s*1024+n];
        #pragma unroll
        for(int s=0;s<8;s++){
          float ww=dvr[s]*__expf(ut+vtf[s]-cv[s]);  // vbar*w_t
          wv[s]=ww; uacc-=ww;
        }
        float utl=ut-la[n];
        #pragma unroll
        for(int s=0;s<8;s++){
          float m=__expf(utl+vm[s]-cv[s]);          // m_t
          float um=uacc*m;
          G[s*1024+n]+=wv[s]+um;
          vacc[s]-=um;
        }
      }
      #pragma unroll
      for(int s=0;s<8;s++) vacc[s]=wsum(vacc[s]);
      if(l==0){
        #pragma unroll
        for(int s=0;s<8;s++) wr[w*8+s]=vacc[s];
      }
      __syncthreads();
      if(tid<8){
        float s0=0.f;
        #pragma unroll
        for(int j=0;j<8;j++) s0+=wr[j*8+tid];
        dv[tid]=s0;
      }
      __syncthreads();
    }
    // C update
    for(int i=tid;i<8192;i+=256) C[i]-=3.0f*G[i];
    __syncthreads();
  }

  // ---- final sinkhorn, warm-started with v from last MESH forward ----
  if(tid<8) dv[tid]=vh[64+tid];
  __syncthreads();
  for(int it=0;it<8;it++){
    float vp[8];
    #pragma unroll
    for(int s=0;s<8;s++) vp[s]=dv[s];
    for(int r=0;r<4;r++){
      int n=r*256+tid;
      float arg[8]; float mx=-1e30f;
      #pragma unroll
      for(int s=0;s<8;s++){ arg[s]=vp[s]-C[s*1024+n]; mx=fmaxf(mx,arg[s]); }
      float ss=0.f;
      #pragma unroll
      for(int s=0;s<8;s++) ss+=__expf(arg[s]-mx);
      du[n]=la[n]-(mx+__logf(ss));
    }
    __syncthreads();
    {
      const float* Cc=C+w*1024;
      float mx=-1e30f;
      for(int i=l;i<1024;i+=32) mx=fmaxf(mx,du[i]-Cc[i]);
      mx=wmax(mx);
      float ss=0.f;
      for(int i=l;i<1024;i+=32) ss+=__expf(du[i]-Cc[i]-mx);
      ss=wsum(ss);
      if(l==0) dv[w]=lb[w]-(mx+__logf(ss));
    }
    __syncthreads();
  }

  // ---- P (into G), attn output on last iter ----
  for(int r=0;r<4;r++){
    int n=r*256+tid;
    float un=du[n];
    #pragma unroll
    for(int s=0;s<8;s++){
      float P=__expf(un+dv[s]-C[s*1024+n]);
      G[s*1024+n]=P;
      if(last) out[OUT_ATTN + b*8192 + s*1024 + n]=P;
    }
  }
  __syncthreads();

  // ---- updates = P @ v  (vectorized over d, split n into halves) ----
  {
    int q4=(tid&15)*4; int sg=tid>>4; int s=sg&7; int h=sg>>3;
    const float4* vp=(const float4*)(g_v+((size_t)(b*1024)+h*512)*64+q4);
    const float* Pr=G+s*1024+h*512;
    float4 acc=make_float4(0.f,0.f,0.f,0.f);
    for(int n=0;n<512;n++){
      float4 vv=vp[(size_t)n*16];
      float p=Pr[n];
      acc.x=fmaf(p,vv.x,acc.x); acc.y=fmaf(p,vv.y,acc.y);
      acc.z=fmaf(p,vv.z,acc.z); acc.w=fmaf(p,vv.w,acc.w);
    }
    du[sg*64+q4+0]=acc.x; du[sg*64+q4+1]=acc.y;
    du[sg*64+q4+2]=acc.z; du[sg*64+q4+3]=acc.w;
  }
  // ---- slot_pos = P @ grid (last iter only) ----
  if(last){
    const float* Pr=G+w*1024;
    float gx=0.f,gy=0.f;
    for(int i=l;i<1024;i+=32){
      float p=Pr[i];
      gx=fmaf(p,(float)(i&31),gx);
      gy=fmaf(p,(float)(i>>5),gy);
    }
    gx=wsum(gx); gy=wsum(gy);
    if(l==0){
      out[OUT_POS+(b*8+w)*2+0]=gx*(1.f/31.f);
      out[OUT_POS+(b*8+w)*2+1]=gy*(1.f/31.f);
    }
  }
  __syncthreads();
  for(int idx=tid;idx<512;idx+=256)
    g_upd[b*512+idx]=du[idx]+du[512+idx];
}

// ---------------- GRU + residual MLP; writes g_slots (and out slots if last) ----------------
__global__ void __launch_bounds__(256) k_gru(
  const float* __restrict__ wih, const float* __restrict__ whh,
  const float* __restrict__ bih, const float* __restrict__ bhh,
  const float* __restrict__ f1w, const float* __restrict__ f1b,
  const float* __restrict__ f2w, const float* __restrict__ f2b,
  const float* __restrict__ lg, const float* __restrict__ lbb,
  float* __restrict__ out, int last){
  __shared__ float up[512], pv[512], gi[1536], gh[1536], hh[512], xn[512], hid[1024];
  int b=blockIdx.x, tid=threadIdx.x, w=tid>>5, l=tid&31;
  for(int i=tid;i<512;i+=256){ up[i]=g_upd[b*512+i]; pv[i]=g_slots[b*512+i]; }
  __syncthreads();
  for(int idx=tid;idx<1536;idx+=256){
    int s=idx/192, j=idx-s*192;
    float a=bih[j], c=bhh[j];
    const float* w1=wih+j*64; const float* w2=whh+j*64;
    const float* us=up+s*64;  const float* ps=pv+s*64;
    #pragma unroll 8
    for(int i=0;i<64;i++){ a=fmaf(us[i],w1[i],a); c=fmaf(ps[i],w2[i],c); }
    gi[idx]=a; gh[idx]=c;
  }
  __syncthreads();
  for(int idx=tid;idx<512;idx+=256){
    int s=idx>>6, d=idx&63;
    float r=sigf(gi[s*192+d]+gh[s*192+d]);
    float z=sigf(gi[s*192+64+d]+gh[s*192+64+d]);
    float nn=tanhf(gi[s*192+128+d]+r*gh[s*192+128+d]);
    hh[idx]=(1.f-z)*nn+z*pv[idx];
  }
  __syncthreads();
  {
    float x0=hh[w*64+l], x1=hh[w*64+l+32];
    float s1=wsum(x0+x1), s2=wsum(x0*x0+x1*x1);
    float m=s1*(1.f/64.f), var=s2*(1.f/64.f)-m*m;
    float rs=rsqrtf(var+1e-5f);
    xn[w*64+l]   =(x0-m)*rs*lg[l]   +lbb[l];
    xn[w*64+l+32]=(x1-m)*rs*lg[l+32]+lbb[l+32];
  }
  __syncthreads();
  for(int idx=tid;idx<1024;idx+=256){
    int s=idx>>7, j=idx&127;
    float a=f1b[j];
    const float* wr1=f1w+j*64; const float* xs=xn+s*64;
    #pragma unroll 8
    for(int i=0;i<64;i++) a=fmaf(xs[i],wr1[i],a);
    hid[idx]=fmaxf(a,0.f);
  }
  __syncthreads();
  for(int idx=tid;idx<512;idx+=256){
    int s=idx>>6, d=idx&63;
    float a=f2b[d];
    const float* wr2=f2w+d*128; const float* hs=hid+s*128;
    #pragma unroll 8
    for(int i=0;i<128;i++) a=fmaf(hs[i],wr2[i],a);
    float val=hh[idx]+a;
    g_slots[b*512+idx]=val;
    if(last) out[b*512+idx]=val;
  }
}

extern "C" void kernel_launch(void* const* d_in, const int* in_sizes, int n_in,
                              void* d_out, int out_size){
  const float* inp  =(const float*)d_in[0];
  const float* noise=(const float*)d_in[1];
  const float* mu   =(const float*)d_in[2];
  const float* sig  =(const float*)d_in[3];
  const float* Wq   =(const float*)d_in[4];
  const float* Wk   =(const float*)d_in[5];
  const float* Wv   =(const float*)d_in[6];
  const float* wih  =(const float*)d_in[7];
  const float* whh  =(const float*)d_in[8];
  const float* bih  =(const float*)d_in[9];
  const float* bhh  =(const float*)d_in[10];
  const float* f1w  =(const float*)d_in[11];
  const float* f1b  =(const float*)d_in[12];
  const float* f2w  =(const float*)d_in[13];
  const float* f2b  =(const float*)d_in[14];
  const float* lig  =(const float*)d_in[15];
  const float* lib  =(const float*)d_in[16];
  const float* lsg  =(const float*)d_in[17];
  const float* lsb  =(const float*)d_in[18];
  const float* lfg  =(const float*)d_in[19];
  const float* lfb  =(const float*)d_in[20];
  const float* wiw  =(const float*)d_in[21];
  const float* wib  =(const float*)d_in[22];
  const float* wsw  =(const float*)d_in[23];
  const float* wsb  =(const float*)d_in[24];
  float* out=(float*)d_out;

  cudaFuncSetAttribute(k_batch, cudaFuncAttributeMaxDynamicSharedMemorySize, SMEM_BYTES);

  k_init_slots<<<(BB*NSL*64+255)/256,256>>>(noise,mu,sig);
  k_prep<<<BB*NN/8,256>>>(inp,lig,lib,Wk,Wv,wiw,wib);
  k_softa<<<BB,256>>>();

  for(int itr=0;itr<3;itr++){
    int last=(itr==2)?1:0;
    k_slotproj<<<BB,256>>>(Wq,lsg,lsb,wsw,wsb);
    k_batch<<<BB,256,SMEM_BYTES>>>(out,last);
    k_gru<<<BB,256>>>(wih,whh,bih,bhh,f1w,f1b,f2w,f2b,lfg,lfb,out,last);
  }
  (void)in_sizes; (void)n_in; (void)out_size;
}

// round 9
// speedup vs baseline: 3.6916x; 3.6916x over previous
#include <cuda_runtime.h>
#include <cuda_bf16.h>
#include <math.h>

#define BB 256
#define NN 1024
#define NSL 8

// ---------------- device-global scratch ----------------
__device__ float g_k[BB*NN*64];
__device__ float g_v[BB*NN*64];
__device__ float g_logits[BB*NN];

__device__ __forceinline__ float wsum(float v){
  #pragma unroll
  for(int o=16;o;o>>=1) v += __shfl_xor_sync(0xffffffffu, v, o);
  return v;
}
__device__ __forceinline__ float wmax(float v){
  #pragma unroll
  for(int o=16;o;o>>=1) v = fmaxf(v, __shfl_xor_sync(0xffffffffu, v, o));
  return v;
}
__device__ __forceinline__ float sigf(float x){ return 1.f/(1.f+__expf(-x)); }

// ================= k_prep: LN(inputs), k/v proj (smem-staged weights), wi logits =================
// 32 rows per CTA, 512 threads, grid = 256*1024/32 = 8192
__global__ void __launch_bounds__(512) k_prep(const float* __restrict__ inp,
        const float* __restrict__ lng, const float* __restrict__ lnb,
        const float* __restrict__ Wk, const float* __restrict__ Wv,
        const float* __restrict__ wiw, const float* __restrict__ wib){
  __shared__ float wk_sm[64*65];
  __shared__ float wv_sm[64*65];
  __shared__ float xs[32*64];
  int row0 = blockIdx.x*32;
  int tid = threadIdx.x, w = tid>>5, l = tid&31;

  // stage weights (padded stride 65 -> conflict-free scalar reads)
  for(int e=tid;e<4096;e+=512){
    int j=e>>6, i=e&63;
    wk_sm[j*65+i]=Wk[e];
    wv_sm[j*65+i]=Wv[e];
  }
  // LN + logits: warp handles rows 2w, 2w+1
  #pragma unroll
  for(int rr=0;rr<2;rr++){
    int row = w*2+rr;
    const float* xr = inp + (size_t)(row0+row)*64;
    float x0=xr[l], x1=xr[l+32];
    float s1=wsum(x0+x1), s2=wsum(x0*x0+x1*x1);
    float m=s1*(1.f/64.f), var=s2*(1.f/64.f)-m*m;
    float rs=rsqrtf(var+1e-5f);
    float n0=(x0-m)*rs*lng[l]+lnb[l];
    float n1=(x1-m)*rs*lng[l+32]+lnb[l+32];
    xs[row*64+l]=n0; xs[row*64+l+32]=n1;
    float lp=wsum(n0*wiw[l]+n1*wiw[l+32]);
    if(l==0) g_logits[row0+row]=lp+wib[0];
  }
  __syncthreads();

  int j=tid&63, rg=tid>>6;   // rg 0..7, rows rg, rg+8, rg+16, rg+24
  float ka[4]={0.f,0.f,0.f,0.f}, va[4]={0.f,0.f,0.f,0.f};
  #pragma unroll 4
  for(int i=0;i<64;i++){
    float wk=wk_sm[j*65+i], wv=wv_sm[j*65+i];
    #pragma unroll
    for(int r=0;r<4;r++){
      float x=xs[(rg+r*8)*64+i];
      ka[r]=fmaf(x,wk,ka[r]);
      va[r]=fmaf(x,wv,va[r]);
    }
  }
  #pragma unroll
  for(int r=0;r<4;r++){
    g_k[(size_t)(row0+rg+r*8)*64+j]=ka[r];
    g_v[(size_t)(row0+rg+r*8)*64+j]=va[r];
  }
}

// ================= k_main: everything else, one CTA per batch element =================
// smem floats: C 8192 | G 8192 | U 8192 | la 1024 | du 1024 | slt 512 | vh 72 | lb 8 | q2 8 | dv 8 | ps 128 | red 16
#define SM_G   8192
#define SM_U   16384
#define SM_LA  24576
#define SM_DU  25600
#define SM_SLT 26624
#define SM_VH  27136
#define SM_LB  27208
#define SM_Q2  27216
#define SM_DV  27224
#define SM_PS  27232
#define SM_RED 27360
#define SM_TOT 27376
#define SMEM_BYTES (SM_TOT*4)

#define OUT_POS  131072
#define OUT_ATTN 135168

__global__ void __launch_bounds__(512,2) k_main(float* __restrict__ out,
  const float* __restrict__ noise, const float* __restrict__ mu, const float* __restrict__ sig,
  const float* __restrict__ Wq,
  const float* __restrict__ lsg, const float* __restrict__ lsb,
  const float* __restrict__ wsw, const float* __restrict__ wsb,
  const float* __restrict__ wih, const float* __restrict__ whh,
  const float* __restrict__ bih, const float* __restrict__ bhh,
  const float* __restrict__ f1w, const float* __restrict__ f1b,
  const float* __restrict__ f2w, const float* __restrict__ f2b,
  const float* __restrict__ lfg, const float* __restrict__ lfb){
  extern __shared__ float sm[];
  float* C   = sm;
  float* G   = sm + SM_G;
  float* U   = sm + SM_U;
  float* la  = sm + SM_LA;
  float* du  = sm + SM_DU;
  float* slt = sm + SM_SLT;
  float* vh  = sm + SM_VH;
  float* lb  = sm + SM_LB;
  float* q2  = sm + SM_Q2;
  float* dv  = sm + SM_DV;
  float* ps  = sm + SM_PS;
  float* red = sm + SM_RED;
  int b=blockIdx.x, tid=threadIdx.x, w=tid>>5, l=tid&31;

  // ---- slots init ----
  { int d=tid&63; slt[tid]=mu[d]+(fabsf(sig[d])+1e-8f)*noise[b*512+tid]; }

  // ---- a = softmax(logits)*8 ; la = log(a+eps) ----
  {
    const float* lg = g_logits + b*1024;
    float mx=-1e30f;
    for(int n=tid;n<1024;n+=512) mx=fmaxf(mx,lg[n]);
    mx=wmax(mx);
    if(l==0) red[w]=mx;
    __syncthreads();
    float M=-1e30f;
    #pragma unroll
    for(int i=0;i<16;i++) M=fmaxf(M,red[i]);
    float ss=0.f;
    for(int n=tid;n<1024;n+=512) ss+=__expf(lg[n]-M);
    ss=wsum(ss);
    if(l==0) ps[w]=ss;
    __syncthreads();
    float S=0.f;
    #pragma unroll
    for(int i=0;i<16;i++) S+=ps[i];
    float invS=8.f/S;
    for(int n=tid;n<1024;n+=512)
      la[n]=__logf(__expf(lg[n]-M)*invS+1e-8f);
  }
  __syncthreads();

  for(int itr=0;itr<3;itr++){
    int last=(itr==2);
    // ---- slotproj: LN(slots) -> sn(U[0..512)), ws logits, q -> du[0..512), q2, lb ----
    float* sn = U;
    if(w<8){
      float x0=slt[w*64+l], x1=slt[w*64+l+32];
      float s1=wsum(x0+x1), s2=wsum(x0*x0+x1*x1);
      float m=s1*(1.f/64.f), var=s2*(1.f/64.f)-m*m;
      float rs=rsqrtf(var+1e-5f);
      float n0=(x0-m)*rs*lsg[l]+lsb[l];
      float n1=(x1-m)*rs*lsg[l+32]+lsb[l+32];
      sn[w*64+l]=n0; sn[w*64+l+32]=n1;
      float lp=wsum(n0*wsw[l]+n1*wsw[l+32]);
      if(l==0) red[w]=lp+wsb[0];
    }
    __syncthreads();
    if(tid==0){
      float M=red[0];
      for(int i=1;i<8;i++) M=fmaxf(M,red[i]);
      float S=0.f;
      for(int i=0;i<8;i++) S+=__expf(red[i]-M);
      for(int i=0;i<8;i++)
        lb[i]=__logf(8.f*__expf(red[i]-M)/S+1e-8f);
    }
    {
      int s=tid>>6, d=tid&63;
      float q=0.f;
      const float4* wq4=(const float4*)(Wq+d*64);
      const float* sns=sn+s*64;
      #pragma unroll
      for(int i4=0;i4<16;i4++){
        float4 ww=wq4[i4];
        q=fmaf(sns[i4*4+0],ww.x,fmaf(sns[i4*4+1],ww.y,fmaf(sns[i4*4+2],ww.z,fmaf(sns[i4*4+3],ww.w,q))));
      }
      __syncthreads();           // sn reads done before du (aliased lifetimes are distinct) ; safe ordering
      du[tid]=q;
      float pq=wsum(q*q);
      if(l==0) ps[w]=pq;
    }
    __syncthreads();
    if(tid<8) q2[tid]=ps[2*tid]+ps[2*tid+1];
    __syncthreads();

    // ---- cdist: C[s][n] ----
    #pragma unroll
    for(int h=0;h<2;h++){
      int n=tid+h*512;
      const float4* kr=(const float4*)(g_k+(size_t)(b*1024+n)*64);
      float dot[8]; float k2=0.f;
      #pragma unroll
      for(int s=0;s<8;s++) dot[s]=0.f;
      #pragma unroll
      for(int i4=0;i4<16;i4++){
        float4 f=kr[i4];
        k2=fmaf(f.x,f.x,fmaf(f.y,f.y,fmaf(f.z,f.z,fmaf(f.w,f.w,k2))));
        #pragma unroll
        for(int s=0;s<8;s++){
          const float* qp=du+s*64+i4*4;
          dot[s]=fmaf(f.x,qp[0],fmaf(f.y,qp[1],fmaf(f.z,qp[2],fmaf(f.w,qp[3],dot[s]))));
        }
      }
      #pragma unroll
      for(int s=0;s<8;s++)
        C[s*1024+n]=sqrtf(fmaxf(k2+q2[s]-2.f*dot[s],1e-12f));
    }
    __syncthreads();

    // ---- MESH ----
    for(int mesh=0;mesh<4;mesh++){
      if(tid<8) vh[tid]=0.f;
      __syncthreads();
      // forward (no max-subtraction; args bounded)
      for(int it=0;it<8;it++){
        float vp[8];
        #pragma unroll
        for(int s=0;s<8;s++) vp[s]=vh[it*8+s];
        #pragma unroll
        for(int h=0;h<2;h++){
          int n=tid+h*512;
          float ss=1e-38f;
          #pragma unroll
          for(int s=0;s<8;s++) ss+=__expf(vp[s]-C[s*1024+n]);
          U[it*1024+n]=la[n]-__logf(ss);
        }
        __syncthreads();
        {
          int s=w>>1, off=(w&1)*512;
          const float* Uc=U+it*1024+off;
          const float* Cc=C+s*1024+off;
          float ss=0.f;
          #pragma unroll 4
          for(int k16=0;k16<16;k16++){
            int i=l+k16*32;
            ss+=__expf(Uc[i]-Cc[i]);
          }
          ss=wsum(ss);
          if(l==0) ps[w]=ss;
        }
        __syncthreads();
        if(tid<8) vh[(it+1)*8+tid]=lb[tid]-__logf(ps[2*tid]+ps[2*tid+1]+1e-38f);
        __syncthreads();
      }
      // entropy direct terms
      {
        float v8[8];
        #pragma unroll
        for(int s=0;s<8;s++) v8[s]=vh[64+s];
        #pragma unroll
        for(int h=0;h<2;h++){
          int n=tid+h*512;
          float u8=U[7*1024+n]; float ra=0.f;
          #pragma unroll
          for(int s=0;s<8;s++){
            float P=__expf(u8+v8[s]-C[s*1024+n]);
            float Pe=P+1e-8f;
            float t0=P*(__logf(Pe)+__fdividef(P,Pe));
            G[s*1024+n]=t0; ra+=t0;
          }
          du[n]=-ra;
        }
        __syncthreads();
        {
          int s=w>>1, off=(w&1)*512;
          const float* Gc=G+s*1024+off;
          float ss=0.f;
          #pragma unroll 4
          for(int k16=0;k16<16;k16++) ss+=Gc[l+k16*32];
          ss=wsum(ss);
          if(l==0) ps[w]=ss;
        }
        __syncthreads();
        if(tid<8) dv[tid]=-(ps[2*tid]+ps[2*tid+1]);
        __syncthreads();
      }
      // backward it = 7..0
      for(int it=7;it>=0;it--){
        float vtf[8],vm[8],dvr[8],vacc[8];
        #pragma unroll
        for(int s=0;s<8;s++){
          vtf[s]=vh[(it+1)*8+s]-lb[s];
          vm[s]=vh[it*8+s];
          dvr[s]=dv[s];
          vacc[s]=0.f;
        }
        #pragma unroll
        for(int h=0;h<2;h++){
          int n=tid+h*512;
          float ut=U[it*1024+n];
          float uacc=(it==7)?du[n]:0.f;
          #pragma unroll
          for(int s=0;s<8;s++){
            float ww=dvr[s]*__expf(ut+vtf[s]-C[s*1024+n]);
            G[s*1024+n]+=ww;
            uacc-=ww;
          }
          float utl=ut-la[n];
          #pragma unroll
          for(int s=0;s<8;s++){
            float m=__expf(utl+vm[s]-C[s*1024+n]);
            float um=uacc*m;
            G[s*1024+n]+=um;
            vacc[s]-=um;
          }
        }
        #pragma unroll
        for(int s=0;s<8;s++) vacc[s]=wsum(vacc[s]);
        if(l==0){
          #pragma unroll
          for(int s=0;s<8;s++) ps[w*8+s]=vacc[s];
        }
        __syncthreads();
        if(tid<8){
          float t=0.f;
          #pragma unroll
          for(int j=0;j<16;j++) t+=ps[j*8+tid];
          dv[tid]=t;
        }
        __syncthreads();
      }
      // C -= lr * grad
      for(int e=tid;e<8192;e+=512) C[e]-=3.0f*G[e];
      __syncthreads();
    }

    // ---- final sinkhorn (warm v) ----
    if(tid<8) dv[tid]=vh[64+tid];
    __syncthreads();
    for(int it=0;it<8;it++){
      float vp[8];
      #pragma unroll
      for(int s=0;s<8;s++) vp[s]=dv[s];
      #pragma unroll
      for(int h=0;h<2;h++){
        int n=tid+h*512;
        float ss=1e-38f;
        #pragma unroll
        for(int s=0;s<8;s++) ss+=__expf(vp[s]-C[s*1024+n]);
        du[n]=la[n]-__logf(ss);
      }
      __syncthreads();
      {
        int s=w>>1, off=(w&1)*512;
        const float* Cc=C+s*1024+off;
        const float* uu=du+off;
        float ss=0.f;
        #pragma unroll 4
        for(int k16=0;k16<16;k16++){
          int i=l+k16*32;
          ss+=__expf(uu[i]-Cc[i]);
        }
        ss=wsum(ss);
        if(l==0) ps[w]=ss;
      }
      __syncthreads();
      if(tid<8) dv[tid]=lb[tid]-__logf(ps[2*tid]+ps[2*tid+1]+1e-38f);
      __syncthreads();
    }

    // ---- P into G (+attn out) ----
    #pragma unroll
    for(int h=0;h<2;h++){
      int n=tid+h*512;
      float un=du[n];
      #pragma unroll
      for(int s=0;s<8;s++){
        float P=__expf(un+dv[s]-C[s*1024+n]);
        G[s*1024+n]=P;
        if(last) out[OUT_ATTN+b*8192+s*1024+n]=P;
      }
    }
    __syncthreads();

    // ---- updates = P @ v via smem v-tiles in U ----
    {
      int s=tid>>6, d=tid&63;
      float acc=0.f;
      const float4* gv4=(const float4*)(g_v+(size_t)b*1024*64);
      float4* U4=(float4*)U;
      for(int t=0;t<8;t++){
        #pragma unroll
        for(int j=0;j<4;j++){
          int idx=tid+j*512;
          U4[idx]=gv4[t*2048+idx];
        }
        __syncthreads();
        const float* Gp=G+s*1024+t*128;
        #pragma unroll 8
        for(int np=0;np<128;np++)
          acc=fmaf(Gp[np],U[np*64+d],acc);
        __syncthreads();
      }
      du[tid]=acc;   // updates[s*64+d]
    }
    // ---- slot_pos (last) ----
    if(last && w<8){
      const float* Pr=G+w*1024;
      float gx=0.f,gy=0.f;
      for(int i=l;i<1024;i+=32){
        float p=Pr[i];
        gx=fmaf(p,(float)(i&31),gx);
        gy=fmaf(p,(float)(i>>5),gy);
      }
      gx=wsum(gx); gy=wsum(gy);
      if(l==0){
        out[OUT_POS+(b*8+w)*2+0]=gx*(1.f/31.f);
        out[OUT_POS+(b*8+w)*2+1]=gy*(1.f/31.f);
      }
    }
    __syncthreads();

    // ---- GRU (gi U[0..1536), gh U[1536..3072)) ----
    #pragma unroll
    for(int k=0;k<3;k++){
      int idx=tid+k*512;
      int s2=idx/192, j=idx-s2*192;
      float a=bih[j], c=bhh[j];
      const float4* w1=(const float4*)(wih+j*64);
      const float4* w2=(const float4*)(whh+j*64);
      const float* us=du+s2*64;
      const float* hs=slt+s2*64;
      #pragma unroll
      for(int i4=0;i4<16;i4++){
        float4 A=w1[i4], Bm=w2[i4];
        a=fmaf(us[i4*4+0],A.x,fmaf(us[i4*4+1],A.y,fmaf(us[i4*4+2],A.z,fmaf(us[i4*4+3],A.w,a))));
        c=fmaf(hs[i4*4+0],Bm.x,fmaf(hs[i4*4+1],Bm.y,fmaf(hs[i4*4+2],Bm.z,fmaf(hs[i4*4+3],Bm.w,c))));
      }
      U[idx]=a; U[1536+idx]=c;
    }
    __syncthreads();
    {
      int s2=tid>>6, d=tid&63;
      float r=sigf(U[s2*192+d]+U[1536+s2*192+d]);
      float z=sigf(U[s2*192+64+d]+U[1536+s2*192+64+d]);
      float nn=tanhf(U[s2*192+128+d]+r*U[1536+s2*192+128+d]);
      U[3072+tid]=(1.f-z)*nn+z*slt[tid];
    }
    __syncthreads();
    // LN(ff) -> U[3584..4096)
    if(w<8){
      float x0=U[3072+w*64+l], x1=U[3072+w*64+l+32];
      float s1=wsum(x0+x1), s2=wsum(x0*x0+x1*x1);
      float m=s1*(1.f/64.f), var=s2*(1.f/64.f)-m*m;
      float rs=rsqrtf(var+1e-5f);
      U[3584+w*64+l]   =(x0-m)*rs*lfg[l]   +lfb[l];
      U[3584+w*64+l+32]=(x1-m)*rs*lfg[l+32]+lfb[l+32];
    }
    __syncthreads();
    // fc1 -> hid U[4096..5120)
    #pragma unroll
    for(int k=0;k<2;k++){
      int idx=tid+k*512;
      int s2=idx>>7, j=idx&127;
      float a=f1b[j];
      const float4* w1=(const float4*)(f1w+j*64);
      const float* xsr=U+3584+s2*64;
      #pragma unroll
      for(int i4=0;i4<16;i4++){
        float4 A=w1[i4];
        a=fmaf(xsr[i4*4+0],A.x,fmaf(xsr[i4*4+1],A.y,fmaf(xsr[i4*4+2],A.z,fmaf(xsr[i4*4+3],A.w,a))));
      }
      U[4096+idx]=fmaxf(a,0.f);
    }
    __syncthreads();
    // fc2 + residual -> slt (and out slots on last)
    {
      int s2=tid>>6, d=tid&63;
      float a=f2b[d];
      const float4* w2=(const float4*)(f2w+d*128);
      const float* hs=U+4096+s2*128;
      #pragma unroll
      for(int i4=0;i4<32;i4++){
        float4 A=w2[i4];
        a=fmaf(hs[i4*4+0],A.x,fmaf(hs[i4*4+1],A.y,fmaf(hs[i4*4+2],A.z,fmaf(hs[i4*4+3],A.w,a))));
      }
      float val=U[3072+tid]+a;
      slt[tid]=val;
      if(last) out[b*512+tid]=val;
    }
    __syncthreads();
  }
}

extern "C" void kernel_launch(void* const* d_in, const int* in_sizes, int n_in,
                              void* d_out, int out_size){
  const float* inp  =(const float*)d_in[0];
  const float* noise=(const float*)d_in[1];
  const float* mu   =(const float*)d_in[2];
  const float* sig  =(const float*)d_in[3];
  const float* Wq   =(const float*)d_in[4];
  const float* Wk   =(const float*)d_in[5];
  const float* Wv   =(const float*)d_in[6];
  const float* wih  =(const float*)d_in[7];
  const float* whh  =(const float*)d_in[8];
  const float* bih  =(const float*)d_in[9];
  const float* bhh  =(const float*)d_in[10];
  const float* f1w  =(const float*)d_in[11];
  const float* f1b  =(const float*)d_in[12];
  const float* f2w  =(const float*)d_in[13];
  const float* f2b  =(const float*)d_in[14];
  const float* lig  =(const float*)d_in[15];
  const float* lib  =(const float*)d_in[16];
  const float* lsg  =(const float*)d_in[17];
  const float* lsb  =(const float*)d_in[18];
  const float* lfg  =(const float*)d_in[19];
  const float* lfb  =(const float*)d_in[20];
  const float* wiw  =(const float*)d_in[21];
  const float* wib  =(const float*)d_in[22];
  const float* wsw  =(const float*)d_in[23];
  const float* wsb  =(const float*)d_in[24];
  float* out=(float*)d_out;

  cudaFuncSetAttribute(k_main, cudaFuncAttributeMaxDynamicSharedMemorySize, SMEM_BYTES);

  k_prep<<<BB*NN/32,512>>>(inp,lig,lib,Wk,Wv,wiw,wib);
  k_main<<<BB,512,SMEM_BYTES>>>(out,noise,mu,sig,Wq,lsg,lsb,wsw,wsb,
                                wih,whh,bih,bhh,f1w,f1b,f2w,f2b,lfg,lfb);
  (void)in_sizes; (void)n_in; (void)out_size;
}

// round 10
// speedup vs baseline: 4.0334x; 1.0926x over previous
#include <cuda_runtime.h>
#include <cuda_bf16.h>
#include <math.h>

#define BB 256
#define NN 1024
#define NSL 8

// ---------------- device-global scratch ----------------
__device__ float g_k[BB*NN*64];
__device__ float g_v[BB*NN*64];
__device__ float g_logits[BB*NN];

__device__ __forceinline__ float wsum(float v){
  #pragma unroll
  for(int o=16;o;o>>=1) v += __shfl_xor_sync(0xffffffffu, v, o);
  return v;
}
__device__ __forceinline__ float wmax(float v){
  #pragma unroll
  for(int o=16;o;o>>=1) v = fmaxf(v, __shfl_xor_sync(0xffffffffu, v, o));
  return v;
}
__device__ __forceinline__ float sigf(float x){ return 1.f/(1.f+__expf(-x)); }
__device__ __forceinline__ float rcpf(float x){ return __fdividef(1.0f, x); }

// ================= k_prep: LN(inputs), k/v proj (smem-staged weights), wi logits =================
__global__ void __launch_bounds__(512) k_prep(const float* __restrict__ inp,
        const float* __restrict__ lng, const float* __restrict__ lnb,
        const float* __restrict__ Wk, const float* __restrict__ Wv,
        const float* __restrict__ wiw, const float* __restrict__ wib){
  __shared__ float wk_sm[64*65];
  __shared__ float wv_sm[64*65];
  __shared__ float xs[32*64];
  int row0 = blockIdx.x*32;
  int tid = threadIdx.x, w = tid>>5, l = tid&31;

  for(int e=tid;e<4096;e+=512){
    int j=e>>6, i=e&63;
    wk_sm[j*65+i]=Wk[e];
    wv_sm[j*65+i]=Wv[e];
  }
  #pragma unroll
  for(int rr=0;rr<2;rr++){
    int row = w*2+rr;
    const float* xr = inp + (size_t)(row0+row)*64;
    float x0=xr[l], x1=xr[l+32];
    float s1=wsum(x0+x1), s2=wsum(x0*x0+x1*x1);
    float m=s1*(1.f/64.f), var=s2*(1.f/64.f)-m*m;
    float rs=rsqrtf(var+1e-5f);
    float n0=(x0-m)*rs*lng[l]+lnb[l];
    float n1=(x1-m)*rs*lng[l+32]+lnb[l+32];
    xs[row*64+l]=n0; xs[row*64+l+32]=n1;
    float lp=wsum(n0*wiw[l]+n1*wiw[l+32]);
    if(l==0) g_logits[row0+row]=lp+wib[0];
  }
  __syncthreads();

  int j=tid&63, rg=tid>>6;
  float ka[4]={0.f,0.f,0.f,0.f}, va[4]={0.f,0.f,0.f,0.f};
  #pragma unroll 4
  for(int i=0;i<64;i++){
    float wk=wk_sm[j*65+i], wv=wv_sm[j*65+i];
    #pragma unroll
    for(int r=0;r<4;r++){
      float x=xs[(rg+r*8)*64+i];
      ka[r]=fmaf(x,wk,ka[r]);
      va[r]=fmaf(x,wv,va[r]);
    }
  }
  #pragma unroll
  for(int r=0;r<4;r++){
    g_k[(size_t)(row0+rg+r*8)*64+j]=ka[r];
    g_v[(size_t)(row0+rg+r*8)*64+j]=va[r];
  }
}

// ================= k_main =================
// smem floats:
#define SO_C   0        // 8192  C, later P
#define SO_E   8192     // 8192  exp(-C), later v-tile stage
#define SO_UH  16384    // 8192  EU history, later GRU scratch
#define SO_A   24576    // 1024  a+eps
#define SO_FU  25600    // 1024  q stage / backward fu / final EU
#define SO_SLT 26624    // 512
#define SO_UPD 27136    // 512
#define SO_EVH 27648    // 80    exp(v_t), t=0..8 (+pad)
#define SO_EB  27728    // 8     b+eps
#define SO_EBI 27736    // 8     1/(b+eps)
#define SO_DV  27744    // 8
#define SO_Q2  27752    // 8
#define SO_WF  27760    // 8
#define SO_EM  27768    // 8
#define SO_PS  27776    // 128
#define SO_RED 27904    // 32
#define SM_TOT 27936
#define SMEM_BYTES (SM_TOT*4)

#define OUT_POS  131072
#define OUT_ATTN 135168

__global__ void __launch_bounds__(512,2) k_main(float* __restrict__ out,
  const float* __restrict__ noise, const float* __restrict__ mu, const float* __restrict__ sig,
  const float* __restrict__ Wq,
  const float* __restrict__ lsg, const float* __restrict__ lsb,
  const float* __restrict__ wsw, const float* __restrict__ wsb,
  const float* __restrict__ wih, const float* __restrict__ whh,
  const float* __restrict__ bih, const float* __restrict__ bhh,
  const float* __restrict__ f1w, const float* __restrict__ f1b,
  const float* __restrict__ f2w, const float* __restrict__ f2b,
  const float* __restrict__ lfg, const float* __restrict__ lfb){
  extern __shared__ float sm[];
  float* C   = sm + SO_C;
  float* E   = sm + SO_E;
  float* UH  = sm + SO_UH;
  float* a_  = sm + SO_A;
  float* fu  = sm + SO_FU;
  float* slt = sm + SO_SLT;
  float* upd = sm + SO_UPD;
  float* EVH = sm + SO_EVH;
  float* eb  = sm + SO_EB;
  float* ebi = sm + SO_EBI;
  float* dv  = sm + SO_DV;
  float* q2  = sm + SO_Q2;
  float* wfs = sm + SO_WF;
  float* ems = sm + SO_EM;
  float* ps  = sm + SO_PS;
  float* red = sm + SO_RED;
  int b=blockIdx.x, tid=threadIdx.x, w=tid>>5, l=tid&31;

  // ---- slots init ----
  { int d=tid&63; slt[tid]=mu[d]+(fabsf(sig[d])+1e-8f)*noise[b*512+tid]; }

  // ---- a = softmax(logits)*8 + eps (value domain) ----
  {
    const float* lg=g_logits+b*1024;
    float mx=-1e30f;
    for(int n=tid;n<1024;n+=512) mx=fmaxf(mx,lg[n]);
    mx=wmax(mx);
    if(l==0) red[w]=mx;
    __syncthreads();
    float M=-1e30f;
    #pragma unroll
    for(int i=0;i<16;i++) M=fmaxf(M,red[i]);
    float ss=0.f;
    for(int n=tid;n<1024;n+=512) ss+=__expf(lg[n]-M);
    ss=wsum(ss);
    if(l==0) ps[w]=ss;
    __syncthreads();
    float S=0.f;
    #pragma unroll
    for(int i=0;i<16;i++) S+=ps[i];
    float invS=8.f/S;
    for(int n=tid;n<1024;n+=512)
      a_[n]=__expf(lg[n]-M)*invS+1e-8f;
  }
  __syncthreads();
  float ia0=rcpf(a_[tid]);
  float ia1=rcpf(a_[tid+512]);

  for(int itr=0;itr<3;itr++){
    int last=(itr==2);
    // ---- slotproj: LN(slots) -> sn (UH), b softmax -> eb/ebi, q -> fu, |q|^2 -> q2 ----
    float* sn = UH;
    if(w<8){
      float x0=slt[w*64+l], x1=slt[w*64+l+32];
      float s1=wsum(x0+x1), s2=wsum(x0*x0+x1*x1);
      float m=s1*(1.f/64.f), var=s2*(1.f/64.f)-m*m;
      float rs=rsqrtf(var+1e-5f);
      float n0=(x0-m)*rs*lsg[l]+lsb[l];
      float n1=(x1-m)*rs*lsg[l+32]+lsb[l+32];
      sn[w*64+l]=n0; sn[w*64+l+32]=n1;
      float lp=wsum(n0*wsw[l]+n1*wsw[l+32]);
      if(l==0) red[w]=lp+wsb[0];
    }
    __syncthreads();
    if(tid==0){
      float M=red[0];
      for(int i=1;i<8;i++) M=fmaxf(M,red[i]);
      float S=0.f;
      for(int i=0;i<8;i++) S+=__expf(red[i]-M);
      for(int i=0;i<8;i++){
        float bb=8.f*__expf(red[i]-M)/S+1e-8f;
        eb[i]=bb; ebi[i]=rcpf(bb);
      }
    }
    float qreg;
    {
      int s=tid>>6, d=tid&63;
      float q=0.f;
      const float4* wq4=(const float4*)(Wq+d*64);
      const float* sns=sn+s*64;
      #pragma unroll
      for(int i4=0;i4<16;i4++){
        float4 ww=wq4[i4];
        q=fmaf(sns[i4*4+0],ww.x,fmaf(sns[i4*4+1],ww.y,fmaf(sns[i4*4+2],ww.z,fmaf(sns[i4*4+3],ww.w,q))));
      }
      qreg=q;
      float pq=wsum(q*q);
      if(l==0) ps[w]=pq;
    }
    __syncthreads();   // sn reads done
    fu[tid]=qreg;
    if(tid<8) q2[tid]=ps[2*tid]+ps[2*tid+1];
    __syncthreads();

    // ---- cdist: C and E=exp(-C) ----
    #pragma unroll
    for(int h=0;h<2;h++){
      int n=tid+h*512;
      const float4* kr=(const float4*)(g_k+(size_t)(b*1024+n)*64);
      float dot[8]; float k2=0.f;
      #pragma unroll
      for(int s=0;s<8;s++) dot[s]=0.f;
      #pragma unroll
      for(int i4=0;i4<16;i4++){
        float4 f=kr[i4];
        k2=fmaf(f.x,f.x,fmaf(f.y,f.y,fmaf(f.z,f.z,fmaf(f.w,f.w,k2))));
        #pragma unroll
        for(int s=0;s<8;s++){
          const float* qp=fu+s*64+i4*4;
          dot[s]=fmaf(f.x,qp[0],fmaf(f.y,qp[1],fmaf(f.z,qp[2],fmaf(f.w,qp[3],dot[s]))));
        }
      }
      #pragma unroll
      for(int s=0;s<8;s++){
        float c=sqrtf(fmaxf(k2+q2[s]-2.f*dot[s],1e-12f));
        C[s*1024+n]=c;
        E[s*1024+n]=__expf(-c);
      }
    }
    __syncthreads();

    // ---- MESH ----
    float du0=0.f, du1=0.f;
    for(int mesh=0;mesh<4;mesh++){
      if(tid<8) EVH[tid]=1.f;   // exp(v_0)=1
      __syncthreads();
      // ---- forward: EU_t, EV_{t+1} ----
      for(int t=0;t<8;t++){
        #pragma unroll
        for(int h=0;h<2;h++){
          int n=tid+h*512;
          float acc=1e-38f;
          #pragma unroll
          for(int s=0;s<8;s++) acc=fmaf(EVH[t*8+s],E[s*1024+n],acc);
          UH[t*1024+n]=a_[n]*rcpf(acc);
        }
        __syncthreads();
        {
          int s=w>>1, base=(w&1)*512;
          const float* Up=UH+t*1024+base;
          const float* Ep=E+s*1024+base;
          float css=0.f;
          #pragma unroll 4
          for(int k16=0;k16<16;k16++){ int i=l+k16*32; css=fmaf(Up[i],Ep[i],css); }
          css=wsum(css);
          if(l==0) ps[w]=css;
        }
        __syncthreads();
        if(tid<8) EVH[(t+1)*8+tid]=eb[tid]*rcpf(ps[2*tid]+ps[2*tid+1]+1e-38f);
        __syncthreads();
      }
      // ---- entropy direct terms: G (regs), du (regs), dv ----
      float G[16];
      #pragma unroll
      for(int h=0;h<2;h++){
        int n=tid+h*512;
        float eu8=UH[7*1024+n];
        float ra=0.f;
        #pragma unroll
        for(int s=0;s<8;s++){
          float P=eu8*EVH[64+s]*E[s*1024+n];
          float Pe=P+1e-8f;
          float t0=P*(__logf(Pe)+P*rcpf(Pe));
          G[h*8+s]=t0; ra+=t0;
        }
        if(h==0) du0=-ra; else du1=-ra;
      }
      #pragma unroll
      for(int s=0;s<8;s++){
        float tv=G[s]+G[8+s];
        tv=wsum(tv);
        if(l==0) ps[w*8+s]=tv;
      }
      __syncthreads();
      if(tid<8){
        float t=0.f;
        #pragma unroll
        for(int j=0;j<16;j++) t+=ps[j*8+tid];
        dv[tid]=-t;
      }
      __syncthreads();
      // ---- backward t=7..0 (no MUFU) ----
      for(int t=7;t>=0;t--){
        if(tid<8){
          wfs[tid]=dv[tid]*EVH[(t+1)*8+tid]*ebi[tid];
          ems[tid]=EVH[t*8+tid];
        }
        __syncthreads();
        #pragma unroll
        for(int h=0;h<2;h++){
          int n=tid+h*512;
          float eut=UH[t*1024+n];
          float e8[8];
          float t1=0.f;
          #pragma unroll
          for(int s=0;s<8;s++){ e8[s]=E[s*1024+n]; t1=fmaf(wfs[s],e8[s],t1); }
          float uacc=((t==7)?(h?du1:du0):0.f)-eut*t1;
          float fun=uacc*eut*(h?ia1:ia0);
          fu[n]=fun;
          #pragma unroll
          for(int s=0;s<8;s++)
            G[h*8+s]=fmaf(e8[s], fmaf(wfs[s],eut, fun*ems[s]), G[h*8+s]);
        }
        __syncthreads();
        {
          int s=w>>1, base=(w&1)*512;
          const float* fp=fu+base;
          const float* Ep=E+s*1024+base;
          float css=0.f;
          #pragma unroll 4
          for(int k16=0;k16<16;k16++){ int i=l+k16*32; css=fmaf(fp[i],Ep[i],css); }
          css=wsum(css);
          if(l==0) ps[w]=css;
        }
        __syncthreads();
        if(tid<8) dv[tid]=-ems[tid]*(ps[2*tid]+ps[2*tid+1]);
        __syncthreads();
      }
      // ---- C -= 3*G ; recompute E ----
      #pragma unroll
      for(int h=0;h<2;h++){
        int n=tid+h*512;
        #pragma unroll
        for(int s=0;s<8;s++){
          float c=C[s*1024+n]-3.0f*G[h*8+s];
          C[s*1024+n]=c;
          E[s*1024+n]=__expf(-c);
        }
      }
      __syncthreads();
    }

    // ---- final sinkhorn (warm exp(v)) ----
    if(tid<8) dv[tid]=EVH[64+tid];
    __syncthreads();
    for(int it=0;it<8;it++){
      #pragma unroll
      for(int h=0;h<2;h++){
        int n=tid+h*512;
        float acc=1e-38f;
        #pragma unroll
        for(int s=0;s<8;s++) acc=fmaf(dv[s],E[s*1024+n],acc);
        fu[n]=a_[n]*rcpf(acc);
      }
      __syncthreads();
      {
        int s=w>>1, base=(w&1)*512;
        const float* fp=fu+base;
        const float* Ep=E+s*1024+base;
        float css=0.f;
        #pragma unroll 4
        for(int k16=0;k16<16;k16++){ int i=l+k16*32; css=fmaf(fp[i],Ep[i],css); }
        css=wsum(css);
        if(l==0) ps[w]=css;
      }
      __syncthreads();
      if(tid<8) dv[tid]=eb[tid]*rcpf(ps[2*tid]+ps[2*tid+1]+1e-38f);
      __syncthreads();
    }

    // ---- P = EU*EV*E into C region (+attn out) ----
    #pragma unroll
    for(int h=0;h<2;h++){
      int n=tid+h*512;
      float eu=fu[n];
      #pragma unroll
      for(int s=0;s<8;s++){
        float P=eu*dv[s]*E[s*1024+n];
        C[s*1024+n]=P;
        if(last) out[OUT_ATTN+b*8192+s*1024+n]=P;
      }
    }
    __syncthreads();

    // ---- slot_pos (last) ----
    if(last){
      int s=w>>1, base=(w&1)*512;
      const float* Pp=C+s*1024+base;
      float gx=0.f,gy=0.f;
      #pragma unroll 4
      for(int k16=0;k16<16;k16++){
        int i=l+k16*32; int n=base+i;
        float p=Pp[i];
        gx=fmaf(p,(float)(n&31),gx);
        gy=fmaf(p,(float)(n>>5),gy);
      }
      gx=wsum(gx); gy=wsum(gy);
      if(l==0){ ps[w]=gx; red[w]=gy; }
    }
    __syncthreads();
    if(last && tid<8){
      out[OUT_POS+(b*8+tid)*2+0]=(ps[2*tid]+ps[2*tid+1])*(1.f/31.f);
      out[OUT_POS+(b*8+tid)*2+1]=(red[2*tid]+red[2*tid+1])*(1.f/31.f);
    }

    // ---- updates = P @ v, v tiles staged into E region ----
    {
      int d=tid&63, s=tid>>6;
      float acc=0.f;
      const float4* gv4=(const float4*)(g_v+(size_t)b*65536);
      float4* E4=(float4*)E;
      for(int t8=0;t8<8;t8++){
        #pragma unroll
        for(int j=0;j<4;j++) E4[tid+j*512]=gv4[t8*2048+tid+j*512];
        __syncthreads();
        const float* Pp=C+s*1024+t8*128;
        #pragma unroll 8
        for(int np=0;np<128;np++)
          acc=fmaf(Pp[np],E[np*64+d],acc);
        __syncthreads();
      }
      upd[tid]=acc;
    }
    __syncthreads();

    // ---- GRU (scratch in UH) ----
    #pragma unroll
    for(int k=0;k<3;k++){
      int idx=tid+k*512;
      int s2=idx/192, j=idx-s2*192;
      float a=bih[j], c=bhh[j];
      const float4* w1=(const float4*)(wih+j*64);
      const float4* w2=(const float4*)(whh+j*64);
      const float* us=upd+s2*64;
      const float* hs=slt+s2*64;
      #pragma unroll
      for(int i4=0;i4<16;i4++){
        float4 A=w1[i4], Bm=w2[i4];
        a=fmaf(us[i4*4+0],A.x,fmaf(us[i4*4+1],A.y,fmaf(us[i4*4+2],A.z,fmaf(us[i4*4+3],A.w,a))));
        c=fmaf(hs[i4*4+0],Bm.x,fmaf(hs[i4*4+1],Bm.y,fmaf(hs[i4*4+2],Bm.z,fmaf(hs[i4*4+3],Bm.w,c))));
      }
      UH[idx]=a; UH[1536+idx]=c;
    }
    __syncthreads();
    {
      int s2=tid>>6, d=tid&63;
      float r=sigf(UH[s2*192+d]+UH[1536+s2*192+d]);
      float z=sigf(UH[s2*192+64+d]+UH[1536+s2*192+64+d]);
      float nn=tanhf(UH[s2*192+128+d]+r*UH[1536+s2*192+128+d]);
      UH[3072+tid]=(1.f-z)*nn+z*slt[tid];
    }
    __syncthreads();
    if(w<8){
      float x0=UH[3072+w*64+l], x1=UH[3072+w*64+l+32];
      float s1=wsum(x0+x1), s2=wsum(x0*x0+x1*x1);
      float m=s1*(1.f/64.f), var=s2*(1.f/64.f)-m*m;
      float rs=rsqrtf(var+1e-5f);
      UH[3584+w*64+l]   =(x0-m)*rs*lfg[l]   +lfb[l];
      UH[3584+w*64+l+32]=(x1-m)*rs*lfg[l+32]+lfb[l+32];
    }
    __syncthreads();
    #pragma unroll
    for(int k=0;k<2;k++){
      int idx=tid+k*512;
      int s2=idx>>7, j=idx&127;
      float a=f1b[j];
      const float4* w1=(const float4*)(f1w+j*64);
      const float* xsr=UH+3584+s2*64;
      #pragma unroll
      for(int i4=0;i4<16;i4++){
        float4 A=w1[i4];
        a=fmaf(xsr[i4*4+0],A.x,fmaf(xsr[i4*4+1],A.y,fmaf(xsr[i4*4+2],A.z,fmaf(xsr[i4*4+3],A.w,a))));
      }
      UH[4096+idx]=fmaxf(a,0.f);
    }
    __syncthreads();
    {
      int s2=tid>>6, d=tid&63;
      float a=f2b[d];
      const float4* w2=(const float4*)(f2w+d*128);
      const float* hs=UH+4096+s2*128;
      #pragma unroll
      for(int i4=0;i4<32;i4++){
        float4 A=w2[i4];
        a=fmaf(hs[i4*4+0],A.x,fmaf(hs[i4*4+1],A.y,fmaf(hs[i4*4+2],A.z,fmaf(hs[i4*4+3],A.w,a))));
      }
      float val=UH[3072+tid]+a;
      slt[tid]=val;
      if(last) out[b*512+tid]=val;
    }
    __syncthreads();
  }
}

extern "C" void kernel_launch(void* const* d_in, const int* in_sizes, int n_in,
                              void* d_out, int out_size){
  const float* inp  =(const float*)d_in[0];
  const float* noise=(const float*)d_in[1];
  const float* mu   =(const float*)d_in[2];
  const float* sig  =(const float*)d_in[3];
  const float* Wq   =(const float*)d_in[4];
  const float* Wk   =(const float*)d_in[5];
  const float* Wv   =(const float*)d_in[6];
  const float* wih  =(const float*)d_in[7];
  const float* whh  =(const float*)d_in[8];
  const float* bih  =(const float*)d_in[9];
  const float* bhh  =(const float*)d_in[10];
  const float* f1w  =(const float*)d_in[11];
  const float* f1b  =(const float*)d_in[12];
  const float* f2w  =(const float*)d_in[13];
  const float* f2b  =(const float*)d_in[14];
  const float* lig  =(const float*)d_in[15];
  const float* lib  =(const float*)d_in[16];
  const float* lsg  =(const float*)d_in[17];
  const float* lsb  =(const float*)d_in[18];
  const float* lfg  =(const float*)d_in[19];
  const float* lfb  =(const float*)d_in[20];
  const float* wiw  =(const float*)d_in[21];
  const float* wib  =(const float*)d_in[22];
  const float* wsw  =(const float*)d_in[23];
  const float* wsb  =(const float*)d_in[24];
  float* out=(float*)d_out;

  cudaFuncSetAttribute(k_main, cudaFuncAttributeMaxDynamicSharedMemorySize, SMEM_BYTES);

  k_prep<<<BB*NN/32,512>>>(inp,lig,lib,Wk,Wv,wiw,wib);
  k_main<<<BB,512,SMEM_BYTES>>>(out,noise,mu,sig,Wq,lsg,lsb,wsw,wsb,
                                wih,whh,bih,bhh,f1w,f1b,f2w,f2b,lfg,lfb);
  (void)in_sizes; (void)n_in; (void)out_size;
}

// round 11
// speedup vs baseline: 7.6457x; 1.8956x over previous
#include <cuda_runtime.h>
#include <cuda_bf16.h>
#include <math.h>

#define BB 256
#define NN 1024
#define NSL 8

// ---------------- device-global scratch ----------------
__device__ float g_kT[BB*64*NN];   // [b][d][n]
__device__ float g_v[BB*NN*64];    // [b][n][d]
__device__ float g_logits[BB*NN];

__device__ __forceinline__ float wsum(float v){
  #pragma unroll
  for(int o=16;o;o>>=1) v += __shfl_xor_sync(0xffffffffu, v, o);
  return v;
}
__device__ __forceinline__ float wmax(float v){
  #pragma unroll
  for(int o=16;o;o>>=1) v = fmaxf(v, __shfl_xor_sync(0xffffffffu, v, o));
  return v;
}
__device__ __forceinline__ float sigf(float x){ return 1.f/(1.f+__expf(-x)); }
__device__ __forceinline__ float rcpf(float x){ return __fdividef(1.0f, x); }

// ================= k_prep: LN(inputs), k/v proj, wi logits; k stored TRANSPOSED =================
__global__ void __launch_bounds__(512) k_prep(const float* __restrict__ inp,
        const float* __restrict__ lng, const float* __restrict__ lnb,
        const float* __restrict__ Wk, const float* __restrict__ Wv,
        const float* __restrict__ wiw, const float* __restrict__ wib){
  __shared__ float wk_sm[64*65];
  __shared__ float wv_sm[64*65];
  __shared__ float xs[32*64];
  int row0 = blockIdx.x*32;
  int tid = threadIdx.x, w = tid>>5, l = tid&31;

  for(int e=tid;e<4096;e+=512){
    int j=e>>6, i=e&63;
    wk_sm[j*65+i]=Wk[e];
    wv_sm[j*65+i]=Wv[e];
  }
  #pragma unroll
  for(int rr=0;rr<2;rr++){
    int row = w*2+rr;
    const float* xr = inp + (size_t)(row0+row)*64;
    float x0=xr[l], x1=xr[l+32];
    float s1=wsum(x0+x1), s2=wsum(x0*x0+x1*x1);
    float m=s1*(1.f/64.f), var=s2*(1.f/64.f)-m*m;
    float rs=rsqrtf(var+1e-5f);
    float n0=(x0-m)*rs*lng[l]+lnb[l];
    float n1=(x1-m)*rs*lng[l+32]+lnb[l+32];
    xs[row*64+l]=n0; xs[row*64+l+32]=n1;
    float lp=wsum(n0*wiw[l]+n1*wiw[l+32]);
    if(l==0) g_logits[row0+row]=lp+wib[0];
  }
  __syncthreads();

  int j=tid&63, rg=tid>>6;
  float ka[4]={0.f,0.f,0.f,0.f}, va[4]={0.f,0.f,0.f,0.f};
  #pragma unroll 4
  for(int i=0;i<64;i++){
    float wk=wk_sm[j*65+i], wv=wv_sm[j*65+i];
    #pragma unroll
    for(int r=0;r<4;r++){
      float x=xs[(rg+r*8)*64+i];
      ka[r]=fmaf(x,wk,ka[r]);
      va[r]=fmaf(x,wv,va[r]);
    }
  }
  #pragma unroll
  for(int r=0;r<4;r++)
    g_v[(size_t)(row0+rg+r*8)*64+j]=va[r];
  __syncthreads();   // wk_sm reads done
  #pragma unroll
  for(int r=0;r<4;r++)
    wk_sm[(rg+r*8)*65+j]=ka[r];
  __syncthreads();
  // transposed, coalesced store of k
  int b = blockIdx.x>>5, nbase = (blockIdx.x&31)*32;
  #pragma unroll
  for(int p=0;p<4;p++){
    int idx=tid+p*512;          // 0..2047
    int d=idx>>5, nl=idx&31;
    g_kT[((size_t)b*64+d)*1024 + nbase + nl] = wk_sm[nl*65+d];
  }
}

// ================= k_main =================
// smem floats:
#define SO_UH  0       // 8192  EU history / P / GRU scratch / sn
#define SO_VT  8192    // 4096  v tiles
#define SO_QS  12288   // 512   q
#define SO_SLT 12800   // 512
#define SO_UPD 13312   // 512
#define SO_EVH 13824   // 80
#define SO_EB  13904   // 8
#define SO_EBI 13912   // 8
#define SO_DV  13920   // 8
#define SO_Q2  13928   // 8
#define SO_PS  13936   // 64
#define SO_RED 14000   // 16
#define SM_TOT 14016
#define SMEM_BYTES (SM_TOT*4)

#define OUT_POS  131072
#define OUT_ATTN 135168

__global__ void __launch_bounds__(256,2) k_main(float* __restrict__ out,
  const float* __restrict__ noise, const float* __restrict__ mu, const float* __restrict__ sig,
  const float* __restrict__ Wq,
  const float* __restrict__ lsg, const float* __restrict__ lsb,
  const float* __restrict__ wsw, const float* __restrict__ wsb,
  const float* __restrict__ wih, const float* __restrict__ whh,
  const float* __restrict__ bih, const float* __restrict__ bhh,
  const float* __restrict__ f1w, const float* __restrict__ f1b,
  const float* __restrict__ f2w, const float* __restrict__ f2b,
  const float* __restrict__ lfg, const float* __restrict__ lfb){
  extern __shared__ float sm[];
  float* UH  = sm + SO_UH;
  float* VT  = sm + SO_VT;
  float* qs  = sm + SO_QS;
  float* slt = sm + SO_SLT;
  float* upd = sm + SO_UPD;
  float* EVH = sm + SO_EVH;
  float* eb  = sm + SO_EB;
  float* ebi = sm + SO_EBI;
  float* dv  = sm + SO_DV;
  float* q2  = sm + SO_Q2;
  float* ps  = sm + SO_PS;
  float* red = sm + SO_RED;
  int b=blockIdx.x, tid=threadIdx.x, w=tid>>5, l=tid&31;

  // ---- slots init ----
  #pragma unroll
  for(int k=0;k<2;k++){
    int idx=tid+k*256; int d=idx&63;
    slt[idx]=mu[d]+(fabsf(sig[d])+1e-8f)*noise[b*512+idx];
  }

  // ---- a = softmax(logits)*8 + eps, kept in registers ----
  float a4[4], ia4[4];
  {
    const float* lg=g_logits+b*1024;
    float lg4[4]; float mx=-1e30f;
    #pragma unroll
    for(int h=0;h<4;h++){ lg4[h]=lg[tid+h*256]; mx=fmaxf(mx,lg4[h]); }
    mx=wmax(mx);
    if(l==0) red[w]=mx;
    __syncthreads();
    float M=-1e30f;
    #pragma unroll
    for(int i=0;i<8;i++) M=fmaxf(M,red[i]);
    float ss=0.f;
    #pragma unroll
    for(int h=0;h<4;h++) ss+=__expf(lg4[h]-M);
    ss=wsum(ss);
    if(l==0) ps[w]=ss;
    __syncthreads();
    float S=0.f;
    #pragma unroll
    for(int i=0;i<8;i++) S+=ps[i];
    float invS=8.f/S;
    #pragma unroll
    for(int h=0;h<4;h++){ a4[h]=__expf(lg4[h]-M)*invS+1e-8f; ia4[h]=rcpf(a4[h]); }
  }
  __syncthreads();

  for(int itr=0;itr<3;itr++){
    int last=(itr==2);

    // ---- slotproj: LN(slots) -> UH[0..512), ws logits ----
    {
      float x0=slt[w*64+l], x1=slt[w*64+l+32];
      float s1=wsum(x0+x1), s2=wsum(x0*x0+x1*x1);
      float m=s1*(1.f/64.f), var=s2*(1.f/64.f)-m*m;
      float rs=rsqrtf(var+1e-5f);
      float n0=(x0-m)*rs*lsg[l]+lsb[l];
      float n1=(x1-m)*rs*lsg[l+32]+lsb[l+32];
      UH[w*64+l]=n0; UH[w*64+l+32]=n1;
      float lp=wsum(n0*wsw[l]+n1*wsw[l+32]);
      if(l==0) red[w]=lp+wsb[0];
    }
    __syncthreads();
    if(tid==0){
      float M=red[0];
      for(int i=1;i<8;i++) M=fmaxf(M,red[i]);
      float S=0.f;
      for(int i=0;i<8;i++) S+=__expf(red[i]-M);
      for(int i=0;i<8;i++){
        float bb=8.f*__expf(red[i]-M)/S+1e-8f;
        eb[i]=bb; ebi[i]=rcpf(bb);
      }
    }
    // ---- q projection (2 outputs/thread) + |q|^2 ----
    {
      float qv[2];
      #pragma unroll
      for(int k=0;k<2;k++){
        int idx=tid+k*256;
        int s=idx>>6, d=idx&63;
        float q=0.f;
        const float4* wq4=(const float4*)(Wq+d*64);
        const float* sns=UH+s*64;
        #pragma unroll
        for(int i4=0;i4<16;i4++){
          float4 ww=wq4[i4];
          q=fmaf(sns[i4*4+0],ww.x,fmaf(sns[i4*4+1],ww.y,fmaf(sns[i4*4+2],ww.z,fmaf(sns[i4*4+3],ww.w,q))));
        }
        qv[k]=q;
        float pq=wsum(q*q);
        if(l==0) ps[k*8+w]=pq;
      }
      __syncthreads();  // sn reads done; ps visible
      qs[tid]=qv[0]; qs[tid+256]=qv[1];
      if(tid<8){
        int base=(tid>>2)*8+(tid&3)*2;
        q2[tid]=ps[base]+ps[base+1];
      }
    }
    __syncthreads();

    // ---- cdist -> E in REGISTERS ----
    float Ereg[32];
    {
      float q2r[8];
      #pragma unroll
      for(int s=0;s<8;s++) q2r[s]=q2[s];
      float dot[32], k2[4];
      #pragma unroll
      for(int i=0;i<32;i++) dot[i]=0.f;
      #pragma unroll
      for(int h=0;h<4;h++) k2[h]=0.f;
      const float* kTb = g_kT + (size_t)b*65536;
      for(int d=0;d<64;d++){
        float qsd[8];
        #pragma unroll
        for(int s=0;s<8;s++) qsd[s]=qs[s*64+d];
        #pragma unroll
        for(int h=0;h<4;h++){
          float kv=kTb[d*1024 + tid + h*256];
          k2[h]=fmaf(kv,kv,k2[h]);
          #pragma unroll
          for(int s=0;s<8;s++) dot[h*8+s]=fmaf(kv,qsd[s],dot[h*8+s]);
        }
      }
      #pragma unroll
      for(int h=0;h<4;h++)
        #pragma unroll
        for(int s=0;s<8;s++)
          Ereg[h*8+s]=__expf(-sqrtf(fmaxf(k2[h]+q2r[s]-2.f*dot[h*8+s],1e-12f)));
    }
    __syncthreads();

    // ---- MESH ----
    float du4[4]={0.f,0.f,0.f,0.f};
    float euL[4];
    for(int mesh=0;mesh<4;mesh++){
      if(tid<8) EVH[tid]=1.f;
      __syncthreads();
      // forward: row update in regs, column sums fused
      for(int t=0;t<8;t++){
        float ev[8];
        #pragma unroll
        for(int s=0;s<8;s++) ev[s]=EVH[t*8+s];
        float colacc[8];
        #pragma unroll
        for(int s=0;s<8;s++) colacc[s]=0.f;
        #pragma unroll
        for(int h=0;h<4;h++){
          int n=tid+h*256;
          float acc=1e-38f;
          #pragma unroll
          for(int s=0;s<8;s++) acc=fmaf(ev[s],Ereg[h*8+s],acc);
          float eu=a4[h]*rcpf(acc);
          UH[t*1024+n]=eu;
          if(t==7) euL[h]=eu;
          #pragma unroll
          for(int s=0;s<8;s++) colacc[s]=fmaf(eu,Ereg[h*8+s],colacc[s]);
        }
        #pragma unroll
        for(int s=0;s<8;s++) colacc[s]=wsum(colacc[s]);
        if(l==0){
          #pragma unroll
          for(int s=0;s<8;s++) ps[w*8+s]=colacc[s];
        }
        __syncthreads();
        if(tid<8){
          float t2=0.f;
          #pragma unroll
          for(int j=0;j<8;j++) t2+=ps[j*8+tid];
          EVH[(t+1)*8+tid]=eb[tid]*rcpf(t2+1e-38f);
        }
        __syncthreads();
      }
      // entropy direct terms
      float Greg[32];
      {
        float ev8[8];
        #pragma unroll
        for(int s=0;s<8;s++) ev8[s]=EVH[64+s];
        float colacc[8];
        #pragma unroll
        for(int s=0;s<8;s++) colacc[s]=0.f;
        #pragma unroll
        for(int h=0;h<4;h++){
          float ra=0.f;
          #pragma unroll
          for(int s=0;s<8;s++){
            float P=euL[h]*ev8[s]*Ereg[h*8+s];
            float Pe=P+1e-8f;
            float t0=P*(__logf(Pe)+P*rcpf(Pe));
            Greg[h*8+s]=t0; ra+=t0; colacc[s]+=t0;
          }
          du4[h]=-ra;
        }
        #pragma unroll
        for(int s=0;s<8;s++) colacc[s]=wsum(colacc[s]);
        if(l==0){
          #pragma unroll
          for(int s=0;s<8;s++) ps[w*8+s]=colacc[s];
        }
        __syncthreads();
        if(tid<8){
          float t2=0.f;
          #pragma unroll
          for(int j=0;j<8;j++) t2+=ps[j*8+tid];
          dv[tid]=-t2;
        }
        __syncthreads();
      }
      // backward t=7..0 (all-register math)
      for(int t=7;t>=0;t--){
        float wfs[8], ems[8];
        #pragma unroll
        for(int s=0;s<8;s++){
          ems[s]=EVH[t*8+s];
          wfs[s]=dv[s]*EVH[(t+1)*8+s]*ebi[s];
        }
        float colacc[8];
        #pragma unroll
        for(int s=0;s<8;s++) colacc[s]=0.f;
        #pragma unroll
        for(int h=0;h<4;h++){
          int n=tid+h*256;
          float eut=UH[t*1024+n];
          float t1=0.f;
          #pragma unroll
          for(int s=0;s<8;s++) t1=fmaf(wfs[s],Ereg[h*8+s],t1);
          float uacc=((t==7)?du4[h]:0.f)-eut*t1;
          float fun=uacc*eut*ia4[h];
          #pragma unroll
          for(int s=0;s<8;s++){
            float x=fun*Ereg[h*8+s];
            Greg[h*8+s]=fmaf(Ereg[h*8+s]*wfs[s],eut,fmaf(x,ems[s],Greg[h*8+s]));
            colacc[s]+=x;
          }
        }
        #pragma unroll
        for(int s=0;s<8;s++) colacc[s]=wsum(colacc[s]);
        if(l==0){
          #pragma unroll
          for(int s=0;s<8;s++) ps[w*8+s]=colacc[s];
        }
        __syncthreads();
        if(tid<8){
          float t2=0.f;
          #pragma unroll
          for(int j=0;j<8;j++) t2+=ps[j*8+tid];
          dv[tid]=-EVH[t*8+tid]*t2;
        }
        __syncthreads();
      }
      // E *= exp(3*G)  (== C -= 3*G)
      #pragma unroll
      for(int i=0;i<32;i++) Ereg[i]*=__expf(3.0f*Greg[i]);
    }

    // ---- final sinkhorn (warm exp(v)) ----
    if(tid<8) dv[tid]=EVH[64+tid];
    __syncthreads();
    for(int it=0;it<8;it++){
      float dvr[8];
      #pragma unroll
      for(int s=0;s<8;s++) dvr[s]=dv[s];
      float colacc[8];
      #pragma unroll
      for(int s=0;s<8;s++) colacc[s]=0.f;
      #pragma unroll
      for(int h=0;h<4;h++){
        float acc=1e-38f;
        #pragma unroll
        for(int s=0;s<8;s++) acc=fmaf(dvr[s],Ereg[h*8+s],acc);
        float eu=a4[h]*rcpf(acc);
        euL[h]=eu;
        #pragma unroll
        for(int s=0;s<8;s++) colacc[s]=fmaf(eu,Ereg[h*8+s],colacc[s]);
      }
      #pragma unroll
      for(int s=0;s<8;s++) colacc[s]=wsum(colacc[s]);
      if(l==0){
        #pragma unroll
        for(int s=0;s<8;s++) ps[w*8+s]=colacc[s];
      }
      __syncthreads();
      if(tid<8){
        float t2=0.f;
        #pragma unroll
        for(int j=0;j<8;j++) t2+=ps[j*8+tid];
        dv[tid]=eb[tid]*rcpf(t2+1e-38f);
      }
      __syncthreads();
    }

    // ---- P = EU*EV*E -> UH (and attn out) ----
    {
      float dvr[8];
      #pragma unroll
      for(int s=0;s<8;s++) dvr[s]=dv[s];
      #pragma unroll
      for(int h=0;h<4;h++){
        int n=tid+h*256;
        #pragma unroll
        for(int s=0;s<8;s++){
          float P=euL[h]*dvr[s]*Ereg[h*8+s];
          UH[s*1024+n]=P;
          if(last) out[OUT_ATTN+b*8192+s*1024+n]=P;
        }
      }
    }
    __syncthreads();

    // ---- slot_pos (last): warp w -> slot w ----
    if(last){
      const float* Pp=UH+w*1024;
      float gx=0.f,gy=0.f;
      #pragma unroll 4
      for(int i=l;i<1024;i+=32){
        float p=Pp[i];
        gx=fmaf(p,(float)(i&31),gx);
        gy=fmaf(p,(float)(i>>5),gy);
      }
      gx=wsum(gx); gy=wsum(gy);
      if(l==0){
        out[OUT_POS+(b*8+w)*2+0]=gx*(1.f/31.f);
        out[OUT_POS+(b*8+w)*2+1]=gy*(1.f/31.f);
      }
    }

    // ---- updates = P @ v via VT tiles ----
    {
      int d=tid&63, sA=tid>>6, sB=sA+4;
      float acc0=0.f, acc1=0.f;
      const float4* gv4=(const float4*)(g_v+(size_t)b*65536);
      float4* VT4=(float4*)VT;
      for(int t16=0;t16<16;t16++){
        #pragma unroll
        for(int j=0;j<4;j++) VT4[tid+j*256]=gv4[t16*1024+tid+j*256];
        __syncthreads();
        const float* PA=UH+sA*1024+t16*64;
        const float* PB=UH+sB*1024+t16*64;
        #pragma unroll 8
        for(int r=0;r<64;r++){
          float vv=VT[r*64+d];
          acc0=fmaf(PA[r],vv,acc0);
          acc1=fmaf(PB[r],vv,acc1);
        }
        __syncthreads();
      }
      upd[tid]=acc0; upd[tid+256]=acc1;
    }
    __syncthreads();

    // ---- GRU (scratch in UH) ----
    #pragma unroll
    for(int k=0;k<6;k++){
      int idx=tid+k*256;
      int s2=idx/192, j=idx-s2*192;
      float a=bih[j], c=bhh[j];
      const float4* w1=(const float4*)(wih+j*64);
      const float4* w2=(const float4*)(whh+j*64);
      const float* us=upd+s2*64;
      const float* hs=slt+s2*64;
      #pragma unroll
      for(int i4=0;i4<16;i4++){
        float4 A=w1[i4], Bm=w2[i4];
        a=fmaf(us[i4*4+0],A.x,fmaf(us[i4*4+1],A.y,fmaf(us[i4*4+2],A.z,fmaf(us[i4*4+3],A.w,a))));
        c=fmaf(hs[i4*4+0],Bm.x,fmaf(hs[i4*4+1],Bm.y,fmaf(hs[i4*4+2],Bm.z,fmaf(hs[i4*4+3],Bm.w,c))));
      }
      UH[idx]=a; UH[1536+idx]=c;
    }
    __syncthreads();
    #pragma unroll
    for(int k=0;k<2;k++){
      int idx=tid+k*256;
      int s2=idx>>6, d=idx&63;
      float r=sigf(UH[s2*192+d]+UH[1536+s2*192+d]);
      float z=sigf(UH[s2*192+64+d]+UH[1536+s2*192+64+d]);
      float nn=tanhf(UH[s2*192+128+d]+r*UH[1536+s2*192+128+d]);
      UH[3072+idx]=(1.f-z)*nn+z*slt[idx];
    }
    __syncthreads();
    // LN(ff)
    {
      float x0=UH[3072+w*64+l], x1=UH[3072+w*64+l+32];
      float s1=wsum(x0+x1), s2=wsum(x0*x0+x1*x1);
      float m=s1*(1.f/64.f), var=s2*(1.f/64.f)-m*m;
      float rs=rsqrtf(var+1e-5f);
      UH[3584+w*64+l]   =(x0-m)*rs*lfg[l]   +lfb[l];
      UH[3584+w*64+l+32]=(x1-m)*rs*lfg[l+32]+lfb[l+32];
    }
    __syncthreads();
    // fc1
    #pragma unroll
    for(int k=0;k<4;k++){
      int idx=tid+k*256;
      int s2=idx>>7, j=idx&127;
      float a=f1b[j];
      const float4* w1=(const float4*)(f1w+j*64);
      const float* xsr=UH+3584+s2*64;
      #pragma unroll
      for(int i4=0;i4<16;i4++){
        float4 A=w1[i4];
        a=fmaf(xsr[i4*4+0],A.x,fmaf(xsr[i4*4+1],A.y,fmaf(xsr[i4*4+2],A.z,fmaf(xsr[i4*4+3],A.w,a))));
      }
      UH[4096+idx]=fmaxf(a,0.f);
    }
    __syncthreads();
    // fc2 + residual
    #pragma unroll
    for(int k=0;k<2;k++){
      int idx=tid+k*256;
      int s2=idx>>6, d=idx&63;
      float a=f2b[d];
      const float4* w2=(const float4*)(f2w+d*128);
      const float* hs=UH+4096+s2*128;
      #pragma unroll
      for(int i4=0;i4<32;i4++){
        float4 A=w2[i4];
        a=fmaf(hs[i4*4+0],A.x,fmaf(hs[i4*4+1],A.y,fmaf(hs[i4*4+2],A.z,fmaf(hs[i4*4+3],A.w,a))));
      }
      float val=UH[3072+idx]+a;
      slt[idx]=val;
      if(last) out[b*512+idx]=val;
    }
    __syncthreads();
  }
}

extern "C" void kernel_launch(void* const* d_in, const int* in_sizes, int n_in,
                              void* d_out, int out_size){
  const float* inp  =(const float*)d_in[0];
  const float* noise=(const float*)d_in[1];
  const float* mu   =(const float*)d_in[2];
  const float* sig  =(const float*)d_in[3];
  const float* Wq   =(const float*)d_in[4];
  const float* Wk   =(const float*)d_in[5];
  const float* Wv   =(const float*)d_in[6];
  const float* wih  =(const float*)d_in[7];
  const float* whh  =(const float*)d_in[8];
  const float* bih  =(const float*)d_in[9];
  const float* bhh  =(const float*)d_in[10];
  const float* f1w  =(const float*)d_in[11];
  const float* f1b  =(const float*)d_in[12];
  const float* f2w  =(const float*)d_in[13];
  const float* f2b  =(const float*)d_in[14];
  const float* lig  =(const float*)d_in[15];
  const float* lib  =(const float*)d_in[16];
  const float* lsg  =(const float*)d_in[17];
  const float* lsb  =(const float*)d_in[18];
  const float* lfg  =(const float*)d_in[19];
  const float* lfb  =(const float*)d_in[20];
  const float* wiw  =(const float*)d_in[21];
  const float* wib  =(const float*)d_in[22];
  const float* wsw  =(const float*)d_in[23];
  const float* wsb  =(const float*)d_in[24];
  float* out=(float*)d_out;

  cudaFuncSetAttribute(k_main, cudaFuncAttributeMaxDynamicSharedMemorySize, SMEM_BYTES);

  k_prep<<<BB*NN/32,512>>>(inp,lig,lib,Wk,Wv,wiw,wib);
  k_main<<<BB,256,SMEM_BYTES>>>(out,noise,mu,sig,Wq,lsg,lsb,wsw,wsb,
                                wih,whh,bih,bhh,f1w,f1b,f2w,f2b,lfg,lfb);
  (void)in_sizes; (void)n_in; (void)out_size;
}

// round 12
// speedup vs baseline: 8.0579x; 1.0539x over previous
#include <cuda_runtime.h>
#include <cuda_bf16.h>
#include <math.h>

#define BB 256
#define NN 1024
#define NSL 8

// ---------------- device-global scratch ----------------
__device__ float g_kT[BB*64*NN];   // [b][d][n]
__device__ float g_v[BB*NN*64];    // [b][n][d]
__device__ float g_logits[BB*NN];

__device__ __forceinline__ float wsum(float v){
  #pragma unroll
  for(int o=16;o;o>>=1) v += __shfl_xor_sync(0xffffffffu, v, o);
  return v;
}
__device__ __forceinline__ float wmax(float v){
  #pragma unroll
  for(int o=16;o;o>>=1) v = fmaxf(v, __shfl_xor_sync(0xffffffffu, v, o));
  return v;
}
__device__ __forceinline__ float sigf(float x){ return 1.f/(1.f+__expf(-x)); }
__device__ __forceinline__ float rcpf(float x){ return __fdividef(1.0f, x); }
__device__ __forceinline__ int br3(int p){ return ((p&1)<<2)|(p&2)|((p&4)>>2); }

// multi-value butterfly: warp-reduce 8 values in 9 shuffles.
// Returns full-warp sum of value br3(l&7).
__device__ __forceinline__ float mred8(const float* c, int l){
  float r1[4], r2[2], r3;
  #pragma unroll
  for(int i=0;i<4;i++){
    float send=(l&1)? c[i] : c[i+4];
    float t=__shfl_xor_sync(0xffffffffu, send, 1);
    r1[i]=((l&1)? c[i+4] : c[i])+t;
  }
  #pragma unroll
  for(int i=0;i<2;i++){
    float send=(l&2)? r1[i] : r1[i+2];
    float t=__shfl_xor_sync(0xffffffffu, send, 2);
    r2[i]=((l&2)? r1[i+2] : r1[i])+t;
  }
  {
    float send=(l&4)? r2[0] : r2[1];
    float t=__shfl_xor_sync(0xffffffffu, send, 4);
    r3=((l&4)? r2[1] : r2[0])+t;
  }
  r3+=__shfl_xor_sync(0xffffffffu, r3, 8);
  r3+=__shfl_xor_sync(0xffffffffu, r3, 16);
  return r3;
}

// ================= k_prep: LN(inputs), k/v proj, wi logits; k stored TRANSPOSED =================
// 64 rows per CTA, 512 threads, grid = 256*16 = 4096
__global__ void __launch_bounds__(512) k_prep(const float* __restrict__ inp,
        const float* __restrict__ lng, const float* __restrict__ lnb,
        const float* __restrict__ Wk, const float* __restrict__ Wv,
        const float* __restrict__ wiw, const float* __restrict__ wib){
  __shared__ float wkT[64*68];
  __shared__ float wvT[64*68];
  __shared__ float xsT[64*68];   // reused as kbuf then vbuf
  int blk=blockIdx.x;
  int b=blk>>4, nb=(blk&15)*64;
  int tid=threadIdx.x, w=tid>>5, l=tid&31;

  // stage transposed weights: wkT[i][j] = Wk[j][i]
  for(int e=tid;e<4096;e+=512){
    int j=e>>6, i=e&63;
    wkT[i*68+j]=Wk[e];
    wvT[i*68+j]=Wv[e];
  }
  // LN + logits: warp w handles rows 4w..4w+3
  #pragma unroll
  for(int rr=0;rr<4;rr++){
    int row=w*4+rr;
    const float* xr=inp+(size_t)(b*1024+nb+row)*64;
    float x0=xr[l], x1=xr[l+32];
    float s1=wsum(x0+x1), s2=wsum(x0*x0+x1*x1);
    float m=s1*(1.f/64.f), var=s2*(1.f/64.f)-m*m;
    float rs=rsqrtf(var+1e-5f);
    float v0=(x0-m)*rs*lng[l]+lnb[l];
    float v1=(x1-m)*rs*lng[l+32]+lnb[l+32];
    xsT[l*68+row]=v0; xsT[(l+32)*68+row]=v1;
    float lp=wsum(v0*wiw[l]+v1*wiw[l+32]);
    if(l==0) g_logits[b*1024+nb+row]=lp+wib[0];
  }
  __syncthreads();

  // GEMM: rp=tid&31 (rows 2rp,2rp+1), j4=(tid>>5)*4 (weight reads broadcast per warp)
  int rp=tid&31, j4=(tid>>5)*4;
  float ka[2][4]={{0.f,0.f,0.f,0.f},{0.f,0.f,0.f,0.f}};
  float va[2][4]={{0.f,0.f,0.f,0.f},{0.f,0.f,0.f,0.f}};
  #pragma unroll 4
  for(int i=0;i<64;i++){
    float2 x2=*(const float2*)&xsT[i*68+rp*2];
    float4 wk4=*(const float4*)&wkT[i*68+j4];
    float4 wv4=*(const float4*)&wvT[i*68+j4];
    ka[0][0]=fmaf(x2.x,wk4.x,ka[0][0]); ka[0][1]=fmaf(x2.x,wk4.y,ka[0][1]);
    ka[0][2]=fmaf(x2.x,wk4.z,ka[0][2]); ka[0][3]=fmaf(x2.x,wk4.w,ka[0][3]);
    ka[1][0]=fmaf(x2.y,wk4.x,ka[1][0]); ka[1][1]=fmaf(x2.y,wk4.y,ka[1][1]);
    ka[1][2]=fmaf(x2.y,wk4.z,ka[1][2]); ka[1][3]=fmaf(x2.y,wk4.w,ka[1][3]);
    va[0][0]=fmaf(x2.x,wv4.x,va[0][0]); va[0][1]=fmaf(x2.x,wv4.y,va[0][1]);
    va[0][2]=fmaf(x2.x,wv4.z,va[0][2]); va[0][3]=fmaf(x2.x,wv4.w,va[0][3]);
    va[1][0]=fmaf(x2.y,wv4.x,va[1][0]); va[1][1]=fmaf(x2.y,wv4.y,va[1][1]);
    va[1][2]=fmaf(x2.y,wv4.z,va[1][2]); va[1][3]=fmaf(x2.y,wv4.w,va[1][3]);
  }
  __syncthreads();   // xsT free
  // kbuf [d][n]
  #pragma unroll
  for(int r=0;r<2;r++)
    #pragma unroll
    for(int jj=0;jj<4;jj++)
      xsT[(j4+jj)*68 + rp*2+r]=ka[r][jj];
  __syncthreads();
  #pragma unroll
  for(int q=0;q<8;q++){
    int o=tid+q*512;
    int d=o>>6, n=o&63;
    g_kT[((size_t)b*64+d)*1024 + nb + n]=xsT[d*68+n];
  }
  __syncthreads();
  // vbuf [n][d]
  #pragma unroll
  for(int r=0;r<2;r++)
    #pragma unroll
    for(int jj=0;jj<4;jj++)
      xsT[(rp*2+r)*68 + j4+jj]=va[r][jj];
  __syncthreads();
  #pragma unroll
  for(int q=0;q<8;q++){
    int o=tid+q*512;
    int n=o>>6, d=o&63;
    g_v[((size_t)(b*1024+nb+n))*64 + d]=xsT[n*68+d];
  }
}

// ================= k_main =================
#define SO_UH  0       // 8192
#define SO_VT  8192    // 4096
#define SO_QS  12288   // 512
#define SO_SLT 12800   // 512
#define SO_UPD 13312   // 512
#define SO_EVH 13824   // 80
#define SO_EB  13904   // 8
#define SO_EBI 13912   // 8
#define SO_Q2  13920   // 8
#define SO_PS  13936   // 128 (double buffer 2x64)
#define SO_EVW 14064   // 64
#define SO_DVW 14128   // 64
#define SO_RED 14192   // 16
#define SM_TOT 14208
#define SMEM_BYTES (SM_TOT*4)

#define OUT_POS  131072
#define OUT_ATTN 135168

__global__ void __launch_bounds__(256,2) k_main(float* __restrict__ out,
  const float* __restrict__ noise, const float* __restrict__ mu, const float* __restrict__ sig,
  const float* __restrict__ Wq,
  const float* __restrict__ lsg, const float* __restrict__ lsb,
  const float* __restrict__ wsw, const float* __restrict__ wsb,
  const float* __restrict__ wih, const float* __restrict__ whh,
  const float* __restrict__ bih, const float* __restrict__ bhh,
  const float* __restrict__ f1w, const float* __restrict__ f1b,
  const float* __restrict__ f2w, const float* __restrict__ f2b,
  const float* __restrict__ lfg, const float* __restrict__ lfb){
  extern __shared__ float sm[];
  float* UH  = sm + SO_UH;
  float* VT  = sm + SO_VT;
  float* qs  = sm + SO_QS;
  float* slt = sm + SO_SLT;
  float* upd = sm + SO_UPD;
  float* EVH = sm + SO_EVH;
  float* eb  = sm + SO_EB;
  float* ebi = sm + SO_EBI;
  float* q2  = sm + SO_Q2;
  float* ps  = sm + SO_PS;
  float* evw = sm + SO_EVW;
  float* dvw = sm + SO_DVW;
  float* red = sm + SO_RED;
  int b=blockIdx.x, tid=threadIdx.x, w=tid>>5, l=tid&31;
  int pbuf=0;

  // ---- slots init ----
  #pragma unroll
  for(int k=0;k<2;k++){
    int idx=tid+k*256; int d=idx&63;
    slt[idx]=mu[d]+(fabsf(sig[d])+1e-8f)*noise[b*512+idx];
  }

  // ---- a = softmax(logits)*8 + eps (registers) ----
  float a4[4], ia4[4];
  {
    const float* lg=g_logits+b*1024;
    float lg4[4]; float mx=-1e30f;
    #pragma unroll
    for(int h=0;h<4;h++){ lg4[h]=lg[tid+h*256]; mx=fmaxf(mx,lg4[h]); }
    mx=wmax(mx);
    if(l==0) red[w]=mx;
    __syncthreads();
    float M=-1e30f;
    #pragma unroll
    for(int i=0;i<8;i++) M=fmaxf(M,red[i]);
    float ss=0.f;
    #pragma unroll
    for(int h=0;h<4;h++) ss+=__expf(lg4[h]-M);
    ss=wsum(ss);
    if(l==0) ps[w]=ss;
    __syncthreads();
    float S=0.f;
    #pragma unroll
    for(int i=0;i<8;i++) S+=ps[i];
    float invS=8.f/S;
    #pragma unroll
    for(int h=0;h<4;h++){ a4[h]=__expf(lg4[h]-M)*invS+1e-8f; ia4[h]=rcpf(a4[h]); }
  }
  __syncthreads();

  for(int itr=0;itr<3;itr++){
    int last=(itr==2);

    // ---- slotproj: LN(slots) -> UH[0..512), ws logits ----
    {
      float x0=slt[w*64+l], x1=slt[w*64+l+32];
      float s1=wsum(x0+x1), s2=wsum(x0*x0+x1*x1);
      float m=s1*(1.f/64.f), var=s2*(1.f/64.f)-m*m;
      float rs=rsqrtf(var+1e-5f);
      float n0=(x0-m)*rs*lsg[l]+lsb[l];
      float n1=(x1-m)*rs*lsg[l+32]+lsb[l+32];
      UH[w*64+l]=n0; UH[w*64+l+32]=n1;
      float lp=wsum(n0*wsw[l]+n1*wsw[l+32]);
      if(l==0) red[w]=lp+wsb[0];
    }
    __syncthreads();
    if(tid==0){
      float M=red[0];
      for(int i=1;i<8;i++) M=fmaxf(M,red[i]);
      float S=0.f;
      for(int i=0;i<8;i++) S+=__expf(red[i]-M);
      for(int i=0;i<8;i++){
        float bb=8.f*__expf(red[i]-M)/S+1e-8f;
        eb[i]=bb; ebi[i]=rcpf(bb);
      }
    }
    // ---- q projection + |q|^2 ----
    {
      float qv[2];
      #pragma unroll
      for(int k=0;k<2;k++){
        int idx=tid+k*256;
        int s=idx>>6, d=idx&63;
        float q=0.f;
        const float4* wq4=(const float4*)(Wq+d*64);
        const float* sns=UH+s*64;
        #pragma unroll
        for(int i4=0;i4<16;i4++){
          float4 ww=wq4[i4];
          q=fmaf(sns[i4*4+0],ww.x,fmaf(sns[i4*4+1],ww.y,fmaf(sns[i4*4+2],ww.z,fmaf(sns[i4*4+3],ww.w,q))));
        }
        qv[k]=q;
        float pq=wsum(q*q);
        if(l==0) ps[k*8+w]=pq;
      }
      __syncthreads();
      qs[tid]=qv[0]; qs[tid+256]=qv[1];
      if(tid<8){
        int base=(tid>>2)*8+(tid&3)*2;
        q2[tid]=ps[base]+ps[base+1];
      }
    }
    __syncthreads();

    // ---- cdist -> E in registers ----
    float Ereg[32];
    {
      float q2r[8];
      #pragma unroll
      for(int s=0;s<8;s++) q2r[s]=q2[s];
      float dot[32], k2[4];
      #pragma unroll
      for(int i=0;i<32;i++) dot[i]=0.f;
      #pragma unroll
      for(int h=0;h<4;h++) k2[h]=0.f;
      const float* kTb = g_kT + (size_t)b*65536;
      for(int d=0;d<64;d++){
        float qsd[8];
        #pragma unroll
        for(int s=0;s<8;s++) qsd[s]=qs[s*64+d];
        #pragma unroll
        for(int h=0;h<4;h++){
          float kv=kTb[d*1024 + tid + h*256];
          k2[h]=fmaf(kv,kv,k2[h]);
          #pragma unroll
          for(int s=0;s<8;s++) dot[h*8+s]=fmaf(kv,qsd[s],dot[h*8+s]);
        }
      }
      #pragma unroll
      for(int h=0;h<4;h++)
        #pragma unroll
        for(int s=0;s<8;s++)
          Ereg[h*8+s]=__expf(-sqrtf(fmaxf(k2[h]+q2r[s]-2.f*dot[h*8+s],1e-12f)));
    }
    __syncthreads();

    // ---- MESH ----
    float du4[4]={0.f,0.f,0.f,0.f};
    float euL[4];
    for(int mesh=0;mesh<4;mesh++){
      if(tid<8) EVH[tid]=1.f;   // exp(v_0)=1 (history slot 0)
      __syncthreads();
      // forward
      for(int t=0;t<8;t++){
        float ev[8];
        if(t==0){
          #pragma unroll
          for(int s=0;s<8;s++) ev[s]=1.f;
        } else {
          #pragma unroll
          for(int s=0;s<8;s++) ev[s]=evw[w*8+s];
        }
        float colacc[8];
        #pragma unroll
        for(int s=0;s<8;s++) colacc[s]=0.f;
        #pragma unroll
        for(int h=0;h<4;h++){
          int n=tid+h*256;
          float acc=1e-38f;
          #pragma unroll
          for(int s=0;s<8;s++) acc=fmaf(ev[s],Ereg[h*8+s],acc);
          float eu=a4[h]*rcpf(acc);
          UH[t*1024+n]=eu;
          if(t==7) euL[h]=eu;
          #pragma unroll
          for(int s=0;s<8;s++) colacc[s]=fmaf(eu,Ereg[h*8+s],colacc[s]);
        }
        float r3=mred8(colacc,l);
        float* pb=ps+(pbuf<<6);
        if(l<8) pb[w*8+br3(l)]=r3;
        __syncthreads();
        if(l<8){
          int vv=br3(l);
          float tot=0.f;
          #pragma unroll
          for(int j=0;j<8;j++) tot+=pb[j*8+vv];
          float evv=eb[vv]*rcpf(tot+1e-38f);
          evw[w*8+vv]=evv;
          if(w==0) EVH[(t+1)*8+vv]=evv;
        }
        __syncwarp();
        pbuf^=1;
      }
      // entropy direct terms
      float Greg[32];
      {
        float ev8[8];
        #pragma unroll
        for(int s=0;s<8;s++) ev8[s]=evw[w*8+s];
        float colacc[8];
        #pragma unroll
        for(int s=0;s<8;s++) colacc[s]=0.f;
        #pragma unroll
        for(int h=0;h<4;h++){
          float ra=0.f;
          #pragma unroll
          for(int s=0;s<8;s++){
            float P=euL[h]*ev8[s]*Ereg[h*8+s];
            float Pe=P+1e-8f;
            float t0=P*(__logf(Pe)+P*rcpf(Pe));
            Greg[h*8+s]=t0; ra+=t0; colacc[s]+=t0;
          }
          du4[h]=-ra;
        }
        float r3=mred8(colacc,l);
        float* pb=ps+(pbuf<<6);
        if(l<8) pb[w*8+br3(l)]=r3;
        __syncthreads();
        if(l<8){
          int vv=br3(l);
          float tot=0.f;
          #pragma unroll
          for(int j=0;j<8;j++) tot+=pb[j*8+vv];
          dvw[w*8+vv]=-tot;
        }
        __syncwarp();
        pbuf^=1;
      }
      // backward t=7..0
      for(int t=7;t>=0;t--){
        float wfs[8], ems[8];
        #pragma unroll
        for(int s=0;s<8;s++){
          ems[s]=EVH[t*8+s];
          wfs[s]=dvw[w*8+s]*EVH[(t+1)*8+s]*ebi[s];
        }
        float colacc[8];
        #pragma unroll
        for(int s=0;s<8;s++) colacc[s]=0.f;
        #pragma unroll
        for(int h=0;h<4;h++){
          int n=tid+h*256;
          float eut=UH[t*1024+n];
          float t1=0.f;
          #pragma unroll
          for(int s=0;s<8;s++) t1=fmaf(wfs[s],Ereg[h*8+s],t1);
          float uacc=((t==7)?du4[h]:0.f)-eut*t1;
          float fun=uacc*eut*ia4[h];
          #pragma unroll
          for(int s=0;s<8;s++){
            float x=fun*Ereg[h*8+s];
            Greg[h*8+s]=fmaf(Ereg[h*8+s]*wfs[s],eut,fmaf(x,ems[s],Greg[h*8+s]));
            colacc[s]+=x;
          }
        }
        float r3=mred8(colacc,l);
        float* pb=ps+(pbuf<<6);
        if(l<8) pb[w*8+br3(l)]=r3;
        __syncthreads();
        if(l<8){
          int vv=br3(l);
          float tot=0.f;
          #pragma unroll
          for(int j=0;j<8;j++) tot+=pb[j*8+vv];
          dvw[w*8+vv]=-EVH[t*8+vv]*tot;
        }
        __syncwarp();
        pbuf^=1;
      }
      // E *= exp(3*G)
      #pragma unroll
      for(int i=0;i<32;i++) Ereg[i]*=__expf(3.0f*Greg[i]);
    }

    // ---- final sinkhorn (warm exp(v)) ----
    for(int it=0;it<8;it++){
      float ev[8];
      if(it==0){
        #pragma unroll
        for(int s=0;s<8;s++) ev[s]=EVH[64+s];
      } else {
        #pragma unroll
        for(int s=0;s<8;s++) ev[s]=evw[w*8+s];
      }
      float colacc[8];
      #pragma unroll
      for(int s=0;s<8;s++) colacc[s]=0.f;
      #pragma unroll
      for(int h=0;h<4;h++){
        float acc=1e-38f;
        #pragma unroll
        for(int s=0;s<8;s++) acc=fmaf(ev[s],Ereg[h*8+s],acc);
        float eu=a4[h]*rcpf(acc);
        if(it==7) euL[h]=eu;
        #pragma unroll
        for(int s=0;s<8;s++) colacc[s]=fmaf(eu,Ereg[h*8+s],colacc[s]);
      }
      float r3=mred8(colacc,l);
      float* pb=ps+(pbuf<<6);
      if(l<8) pb[w*8+br3(l)]=r3;
      __syncthreads();
      if(l<8){
        int vv=br3(l);
        float tot=0.f;
        #pragma unroll
        for(int j=0;j<8;j++) tot+=pb[j*8+vv];
        evw[w*8+vv]=eb[vv]*rcpf(tot+1e-38f);
      }
      __syncwarp();
      pbuf^=1;
    }

    // ---- P = EU*EV*E -> UH (and attn out) ----
    {
      float evf[8];
      #pragma unroll
      for(int s=0;s<8;s++) evf[s]=evw[w*8+s];
      #pragma unroll
      for(int h=0;h<4;h++){
        int n=tid+h*256;
        #pragma unroll
        for(int s=0;s<8;s++){
          float P=euL[h]*evf[s]*Ereg[h*8+s];
          UH[s*1024+n]=P;
          if(last) out[OUT_ATTN+b*8192+s*1024+n]=P;
        }
      }
    }
    __syncthreads();

    // ---- slot_pos (last): warp w -> slot w ----
    if(last){
      const float* Pp=UH+w*1024;
      float gx=0.f,gy=0.f;
      #pragma unroll 4
      for(int i=l;i<1024;i+=32){
        float p=Pp[i];
        gx=fmaf(p,(float)(i&31),gx);
        gy=fmaf(p,(float)(i>>5),gy);
      }
      gx=wsum(gx); gy=wsum(gy);
      if(l==0){
        out[OUT_POS+(b*8+w)*2+0]=gx*(1.f/31.f);
        out[OUT_POS+(b*8+w)*2+1]=gy*(1.f/31.f);
      }
    }

    // ---- updates = P @ v via VT tiles ----
    {
      int d=tid&63, sA=tid>>6, sB=sA+4;
      float acc0=0.f, acc1=0.f;
      const float4* gv4=(const float4*)(g_v+(size_t)b*65536);
      float4* VT4=(float4*)VT;
      for(int t16=0;t16<16;t16++){
        #pragma unroll
        for(int j=0;j<4;j++) VT4[tid+j*256]=gv4[t16*1024+tid+j*256];
        __syncthreads();
        const float* PA=UH+sA*1024+t16*64;
        const float* PB=UH+sB*1024+t16*64;
        #pragma unroll 8
        for(int r=0;r<64;r++){
          float vv=VT[r*64+d];
          acc0=fmaf(PA[r],vv,acc0);
          acc1=fmaf(PB[r],vv,acc1);
        }
        __syncthreads();
      }
      upd[tid]=acc0; upd[tid+256]=acc1;
    }
    __syncthreads();

    // ---- GRU (scratch in UH) ----
    #pragma unroll
    for(int k=0;k<6;k++){
      int idx=tid+k*256;
      int s2=idx/192, j=idx-s2*192;
      float a=bih[j], c=bhh[j];
      const float4* w1=(const float4*)(wih+j*64);
      const float4* w2=(const float4*)(whh+j*64);
      const float* us=upd+s2*64;
      const float* hs=slt+s2*64;
      #pragma unroll
      for(int i4=0;i4<16;i4++){
        float4 A=w1[i4], Bm=w2[i4];
        a=fmaf(us[i4*4+0],A.x,fmaf(us[i4*4+1],A.y,fmaf(us[i4*4+2],A.z,fmaf(us[i4*4+3],A.w,a))));
        c=fmaf(hs[i4*4+0],Bm.x,fmaf(hs[i4*4+1],Bm.y,fmaf(hs[i4*4+2],Bm.z,fmaf(hs[i4*4+3],Bm.w,c))));
      }
      UH[idx]=a; UH[1536+idx]=c;
    }
    __syncthreads();
    #pragma unroll
    for(int k=0;k<2;k++){
      int idx=tid+k*256;
      int s2=idx>>6, d=idx&63;
      float r=sigf(UH[s2*192+d]+UH[1536+s2*192+d]);
      float z=sigf(UH[s2*192+64+d]+UH[1536+s2*192+64+d]);
      float nn=tanhf(UH[s2*192+128+d]+r*UH[1536+s2*192+128+d]);
      UH[3072+idx]=(1.f-z)*nn+z*slt[idx];
    }
    __syncthreads();
    // LN(ff)
    {
      float x0=UH[3072+w*64+l], x1=UH[3072+w*64+l+32];
      float s1=wsum(x0+x1), s2=wsum(x0*x0+x1*x1);
      float m=s1*(1.f/64.f), var=s2*(1.f/64.f)-m*m;
      float rs=rsqrtf(var+1e-5f);
      UH[3584+w*64+l]   =(x0-m)*rs*lfg[l]   +lfb[l];
      UH[3584+w*64+l+32]=(x1-m)*rs*lfg[l+32]+lfb[l+32];
    }
    __syncthreads();
    // fc1
    #pragma unroll
    for(int k=0;k<4;k++){
      int idx=tid+k*256;
      int s2=idx>>7, j=idx&127;
      float a=f1b[j];
      const float4* w1=(const float4*)(f1w+j*64);
      const float* xsr=UH+3584+s2*64;
      #pragma unroll
      for(int i4=0;i4<16;i4++){
        float4 A=w1[i4];
        a=fmaf(xsr[i4*4+0],A.x,fmaf(xsr[i4*4+1],A.y,fmaf(xsr[i4*4+2],A.z,fmaf(xsr[i4*4+3],A.w,a))));
      }
      UH[4096+idx]=fmaxf(a,0.f);
    }
    __syncthreads();
    // fc2 + residual
    #pragma unroll
    for(int k=0;k<2;k++){
      int idx=tid+k*256;
      int s2=idx>>6, d=idx&63;
      float a=f2b[d];
      const float4* w2=(const float4*)(f2w+d*128);
      const float* hs=UH+4096+s2*128;
      #pragma unroll
      for(int i4=0;i4<32;i4++){
        float4 A=w2[i4];
        a=fmaf(hs[i4*4+0],A.x,fmaf(hs[i4*4+1],A.y,fmaf(hs[i4*4+2],A.z,fmaf(hs[i4*4+3],A.w,a))));
      }
      float val=UH[3072+idx]+a;
      slt[idx]=val;
      if(last) out[b*512+idx]=val;
    }
    __syncthreads();
  }
}

extern "C" void kernel_launch(void* const* d_in, const int* in_sizes, int n_in,
                              void* d_out, int out_size){
  const float* inp  =(const float*)d_in[0];
  const float* noise=(const float*)d_in[1];
  const float* mu   =(const float*)d_in[2];
  const float* sig  =(const float*)d_in[3];
  const float* Wq   =(const float*)d_in[4];
  const float* Wk   =(const float*)d_in[5];
  const float* Wv   =(const float*)d_in[6];
  const float* wih  =(const float*)d_in[7];
  const float* whh  =(const float*)d_in[8];
  const float* bih  =(const float*)d_in[9];
  const float* bhh  =(const float*)d_in[10];
  const float* f1w  =(const float*)d_in[11];
  const float* f1b  =(const float*)d_in[12];
  const float* f2w  =(const float*)d_in[13];
  const float* f2b  =(const float*)d_in[14];
  const float* lig  =(const float*)d_in[15];
  const float* lib  =(const float*)d_in[16];
  const float* lsg  =(const float*)d_in[17];
  const float* lsb  =(const float*)d_in[18];
  const float* lfg  =(const float*)d_in[19];
  const float* lfb  =(const float*)d_in[20];
  const float* wiw  =(const float*)d_in[21];
  const float* wib  =(const float*)d_in[22];
  const float* wsw  =(const float*)d_in[23];
  const float* wsb  =(const float*)d_in[24];
  float* out=(float*)d_out;

  cudaFuncSetAttribute(k_main, cudaFuncAttributeMaxDynamicSharedMemorySize, SMEM_BYTES);

  k_prep<<<BB*16,512>>>(inp,lig,lib,Wk,Wv,wiw,wib);
  k_main<<<BB,256,SMEM_BYTES>>>(out,noise,mu,sig,Wq,lsg,lsb,wsw,wsb,
                                wih,whh,bih,bhh,f1w,f1b,f2w,f2b,lfg,lfb);
  (void)in_sizes; (void)n_in; (void)out_size;
}